// round 10
// baseline (speedup 1.0000x reference)
#include <cuda_runtime.h>
#include <cuda_bf16.h>
#include <math.h>
#include <stdint.h>

#define NTOK 4096
#define EMB  1024
#define HID  4096
#define VOCAB 32000
#define SEQ  2048
#define NH   16
#define HD   64
#define NL   8

typedef __nv_bfloat16 bf16;
typedef __nv_bfloat162 bf162;

// ---------------- device scratch --------------------------------------------
__device__ __align__(16) float g_x[NTOK * EMB];
__device__ __align__(16) float g_qkv[NTOK * 3 * EMB];

__device__ __align__(16) bf16 g_h_h[NTOK * EMB];
__device__ __align__(16) bf16 g_h_l[NTOK * EMB];
__device__ __align__(16) bf16 g_o_h[NTOK * EMB];
__device__ __align__(16) bf16 g_o_l[NTOK * EMB];
__device__ __align__(16) bf16 g_u_h[NTOK * HID];
__device__ __align__(16) bf16 g_u_l[NTOK * HID];

// transposed weights [N][K] hi/lo; QKV fused to [3E][E] per layer
__device__ __align__(16) bf16 g_Wqkv_h[NL * 3 * EMB * EMB];
__device__ __align__(16) bf16 g_Wqkv_l[NL * 3 * EMB * EMB];
__device__ __align__(16) bf16 g_Wp_h[NL * EMB * EMB];
__device__ __align__(16) bf16 g_Wp_l[NL * EMB * EMB];
__device__ __align__(16) bf16 g_W1_h[NL * EMB * HID];
__device__ __align__(16) bf16 g_W1_l[NL * EMB * HID];
__device__ __align__(16) bf16 g_W2_h[NL * EMB * HID];
__device__ __align__(16) bf16 g_W2_l[NL * EMB * HID];
__device__ __align__(16) bf16 g_Wo_h[(size_t)VOCAB * EMB];
__device__ __align__(16) bf16 g_Wo_l[(size_t)VOCAB * EMB];

// ---------------- helpers ---------------------------------------------------
__device__ __forceinline__ uint32_t smem_u32(const void* p) {
    return (uint32_t)__cvta_generic_to_shared((void*)p);
}
__device__ __forceinline__ uint32_t pack_bf2(float a, float b) {
    bf162 t = __floats2bfloat162_rn(a, b);
    return *reinterpret_cast<uint32_t*>(&t);
}
__device__ __forceinline__ void cpa16(uint32_t dst, const void* src) {
    asm volatile("cp.async.ca.shared.global [%0], [%1], 16;" :: "r"(dst), "l"(src));
}
#define CPA_COMMIT() asm volatile("cp.async.commit_group;" ::: "memory")
#define CPA_WAIT1()  asm volatile("cp.async.wait_group 1;" ::: "memory")

#define LDSM4(r, a) \
    asm volatile("ldmatrix.sync.aligned.m8n8.x4.shared.b16 {%0,%1,%2,%3}, [%4];" \
        : "=r"((r)[0]), "=r"((r)[1]), "=r"((r)[2]), "=r"((r)[3]) : "r"(a))

#define MMA16816(d, a, b) \
    asm volatile("mma.sync.aligned.m16n8k16.row.col.f32.bf16.bf16.f32 " \
        "{%0,%1,%2,%3},{%4,%5,%6,%7},{%8,%9},{%0,%1,%2,%3};" \
        : "+f"((d)[0]), "+f"((d)[1]), "+f"((d)[2]), "+f"((d)[3]) \
        : "r"((a)[0]), "r"((a)[1]), "r"((a)[2]), "r"((a)[3]), \
          "r"((b)[0]), "r"((b)[1]))

// ---------------- all-weights transpose + split-convert ----------------------
__global__ void tconv_all(const float* __restrict__ Wq, const float* __restrict__ Wk,
                          const float* __restrict__ Wv, const float* __restrict__ Wp,
                          const float* __restrict__ W1, const float* __restrict__ W2,
                          const float* __restrict__ Wout,
                          bf16* __restrict__ qkvh, bf16* __restrict__ qkvl,
                          bf16* __restrict__ wph, bf16* __restrict__ wpl,
                          bf16* __restrict__ w1h, bf16* __restrict__ w1l,
                          bf16* __restrict__ w2h, bf16* __restrict__ w2l,
                          bf16* __restrict__ woh, bf16* __restrict__ wol) {
    __shared__ float t[32][33];
    int b = blockIdx.x;
    const float* src; bf16 *oh, *ol;
    int K, N, tilesX, tloc, rowOff = 0;

    if (b < 24576) {
        int type = b / 8192, lb = b % 8192;
        int layer = lb / 1024; tloc = lb % 1024;
        K = 1024; N = 1024; tilesX = 32;
        src = (type == 0 ? Wq : type == 1 ? Wk : Wv) + (size_t)layer * EMB * EMB;
        oh = qkvh + (size_t)layer * 3 * EMB * EMB;
        ol = qkvl + (size_t)layer * 3 * EMB * EMB;
        rowOff = type * 1024;
    } else if (b < 32768) {
        int lb = b - 24576;
        int layer = lb / 1024; tloc = lb % 1024;
        K = 1024; N = 1024; tilesX = 32;
        src = Wp + (size_t)layer * EMB * EMB;
        oh = wph + (size_t)layer * EMB * EMB;
        ol = wpl + (size_t)layer * EMB * EMB;
    } else if (b < 65536) {
        int lb = b - 32768;
        int layer = lb / 4096; tloc = lb % 4096;
        K = 1024; N = 4096; tilesX = 128;
        src = W1 + (size_t)layer * EMB * HID;
        oh = w1h + (size_t)layer * EMB * HID;
        ol = w1l + (size_t)layer * EMB * HID;
    } else if (b < 98304) {
        int lb = b - 65536;
        int layer = lb / 4096; tloc = lb % 4096;
        K = 4096; N = 1024; tilesX = 32;
        src = W2 + (size_t)layer * HID * EMB;
        oh = w2h + (size_t)layer * HID * EMB;
        ol = w2l + (size_t)layer * HID * EMB;
    } else {
        tloc = b - 98304;
        K = 1024; N = VOCAB; tilesX = 1000;
        src = Wout; oh = woh; ol = wol;
    }

    int bx = (tloc % tilesX) * 32;
    int by = (tloc / tilesX) * 32;
    int x = threadIdx.x, y = threadIdx.y;
    #pragma unroll
    for (int i = 0; i < 4; i++)
        t[y + i * 8][x] = src[(size_t)(by + y + i * 8) * N + bx + x];
    __syncthreads();
    #pragma unroll
    for (int i = 0; i < 4; i++) {
        int n = bx + y + i * 8, k = by + x;
        float v = t[x][y + i * 8];
        bf16 hv = __float2bfloat16(v);
        oh[(size_t)(rowOff + n) * K + k] = hv;
        ol[(size_t)(rowOff + n) * K + k] = __float2bfloat16(v - __bfloat162float(hv));
    }
}

// ---------------- embed ------------------------------------------------------
__global__ void embed_kernel(const int* __restrict__ idx, const float* __restrict__ tok,
                             const float* __restrict__ pos, float* __restrict__ x) {
    int n = blockIdx.x, e4 = threadIdx.x, t = n & (SEQ - 1);
    float4 a = ((const float4*)(tok + (size_t)idx[n] * EMB))[e4];
    float4 b = ((const float4*)(pos + (size_t)t * EMB))[e4];
    a.x += b.x; a.y += b.y; a.z += b.z; a.w += b.w;
    ((float4*)(x + (size_t)n * EMB))[e4] = a;
}

// ---------------- layernorm -> hi/lo bf16 ------------------------------------
__device__ __forceinline__ float block_sum_256(float s, float* red) {
    #pragma unroll
    for (int o = 16; o; o >>= 1) s += __shfl_xor_sync(0xffffffffu, s, o);
    if ((threadIdx.x & 31) == 0) red[threadIdx.x >> 5] = s;
    __syncthreads();
    if (threadIdx.x < 32) {
        float t = (threadIdx.x < 8) ? red[threadIdx.x] : 0.0f;
        #pragma unroll
        for (int o = 4; o; o >>= 1) t += __shfl_xor_sync(0xffffffffu, t, o);
        if (threadIdx.x == 0) red[0] = t;
    }
    __syncthreads();
    float r = red[0];
    __syncthreads();
    return r;
}

__global__ void ln_kernel(const float* __restrict__ x, const float* __restrict__ g,
                          const float* __restrict__ b, bf16* __restrict__ oh,
                          bf16* __restrict__ ol) {
    __shared__ float red[8];
    int n = blockIdx.x, tid = threadIdx.x;
    float4 v = ((const float4*)(x + (size_t)n * EMB))[tid];
    float mu = block_sum_256(v.x + v.y + v.z + v.w, red) * (1.0f / EMB);
    float dx = v.x - mu, dy = v.y - mu, dz = v.z - mu, dw = v.w - mu;
    float var = block_sum_256(dx*dx + dy*dy + dz*dz + dw*dw, red) * (1.0f / EMB);
    float rs = rsqrtf(var + 1e-5f);
    float4 gg = ((const float4*)g)[tid];
    float4 bb = ((const float4*)b)[tid];
    float r0 = dx*rs*gg.x + bb.x, r1 = dy*rs*gg.y + bb.y;
    float r2 = dz*rs*gg.z + bb.z, r3 = dw*rs*gg.w + bb.w;
    float h0 = __bfloat162float(__float2bfloat16(r0));
    float h1 = __bfloat162float(__float2bfloat16(r1));
    float h2 = __bfloat162float(__float2bfloat16(r2));
    float h3 = __bfloat162float(__float2bfloat16(r3));
    size_t o = (size_t)n * EMB + tid * 4;
    *(uint2*)(oh + o) = make_uint2(pack_bf2(r0, r1), pack_bf2(r2, r3));
    *(uint2*)(ol + o) = make_uint2(pack_bf2(r0 - h0, r1 - h1), pack_bf2(r2 - h2, r3 - h3));
}

// ========= 16-warp BK=64 / 3-stage ring split-bf16 MMA GEMM ==================
// 128x128 CTA, BK=64 (two 32KB substages per 64KB stage), 512 threads,
// warp tile 32x32, ONE __syncthreads per 64 K, fragments double-buffered
// across all 4 kk-slices and across the stage boundary.
#define FLAG_BIAS 1
#define FLAG_GELU 2
#define FLAG_RES  4
#define FLAG_OSPL 8
#define MG_SMEM (3 * 65536)

__global__ __launch_bounds__(512, 1) void mgemm7_kernel(
    const bf16* __restrict__ Ah, const bf16* __restrict__ Al,
    const bf16* __restrict__ Bh, const bf16* __restrict__ Bl,
    const float* __restrict__ bias, const float* __restrict__ res,
    float* __restrict__ C, bf16* __restrict__ Oh, bf16* __restrict__ Ol,
    int M, int N, int K, int flags) {
    extern __shared__ char sm[];
    uint32_t smb = smem_u32(sm);

    int tid = threadIdx.x;
    int lane = tid & 31, wid = tid >> 5;
    int warp_m = wid >> 2, warp_n = wid & 3;
    int rowBase = blockIdx.x * 128, colBase = blockIdx.y * 128;

    float acc[2][4][4];
    #pragma unroll
    for (int i = 0; i < 2; i++)
        #pragma unroll
        for (int j = 0; j < 4; j++)
            #pragma unroll
            for (int q = 0; q < 4; q++) acc[i][j][q] = 0.0f;

    // LDSM offsets within a 32KB substage: [kk][slot][hi/lo]
    uint32_t offA[2][2][2], offB[2][2][2];
    #pragma unroll
    for (int kk = 0; kk < 2; ++kk) {
        #pragma unroll
        for (int mt = 0; mt < 2; ++mt) {
            int r = warp_m * 32 + mt * 16 + (lane & 15);
            int ch = kk * 2 + (lane >> 4);
            offA[kk][mt][0] = (uint32_t)(r * 128 + ((ch ^ (r & 7)) * 16));
            offA[kk][mt][1] = (uint32_t)(r * 128 + (((ch + 4) ^ (r & 7)) * 16));
        }
        #pragma unroll
        for (int g2 = 0; g2 < 2; ++g2) {
            int n = warp_n * 32 + g2 * 16 + ((lane >> 4) << 3) + (lane & 7);
            int ch = kk * 2 + ((lane >> 3) & 1);
            offB[kk][g2][0] = (uint32_t)(16384 + n * 128 + ((ch ^ (n & 7)) * 16));
            offB[kk][g2][1] = (uint32_t)(16384 + n * 128 + (((ch + 4) ^ (n & 7)) * 16));
        }
    }

    int S = K >> 6;                      // 64-wide stages

    // load one 64KB stage (both substages), one commit group
    auto load_stage = [&](int s, int buf) {
        uint32_t sb = smb + buf * 65536;
        #pragma unroll
        for (int sub = 0; sub < 2; ++sub) {
            const bf16* gAh = Ah + (size_t)rowBase * K + s * 64 + sub * 32;
            const bf16* gAl = Al + (size_t)rowBase * K + s * 64 + sub * 32;
            const bf16* gBh = Bh + (size_t)colBase * K + s * 64 + sub * 32;
            const bf16* gBl = Bl + (size_t)colBase * K + s * 64 + sub * 32;
            uint32_t sbb = sb + sub * 32768;
            #pragma unroll
            for (int i = 0; i < 2; i++) {
                int f = tid + i * 512;
                int r = f >> 3, c = f & 7;
                uint32_t so = (uint32_t)(r * 128 + ((c ^ (r & 7)) * 16));
                const bf16* srcA = (c < 4) ? (gAh + (size_t)r * K + c * 8)
                                           : (gAl + (size_t)r * K + (c - 4) * 8);
                const bf16* srcB = (c < 4) ? (gBh + (size_t)r * K + c * 8)
                                           : (gBl + (size_t)r * K + (c - 4) * 8);
                cpa16(sbb + so, srcA);
                cpa16(sbb + 16384 + so, srcB);
            }
        }
        CPA_COMMIT();
    };

    // register frag double buffers
    uint32_t ah[2][2][4], al[2][2][4], bh[2][8], bl[2][8];

    auto ldfrags = [&](int fb, int kk, uint32_t sb) {
        #pragma unroll
        for (int mt = 0; mt < 2; ++mt) {
            LDSM4(ah[fb][mt], sb + offA[kk][mt][0]);
            LDSM4(al[fb][mt], sb + offA[kk][mt][1]);
        }
        #pragma unroll
        for (int g2 = 0; g2 < 2; ++g2) {
            LDSM4(&bh[fb][g2 * 4], sb + offB[kk][g2][0]);
            LDSM4(&bl[fb][g2 * 4], sb + offB[kk][g2][1]);
        }
    };

    auto do_mma = [&](int fb) {
        #pragma unroll
        for (int mt = 0; mt < 2; ++mt)
            #pragma unroll
            for (int nt = 0; nt < 4; ++nt) {
                uint32_t* ph = &bh[fb][(nt >> 1) * 4 + (nt & 1) * 2];
                uint32_t* pl = &bl[fb][(nt >> 1) * 4 + (nt & 1) * 2];
                MMA16816(acc[mt][nt], ah[fb][mt], ph);
                MMA16816(acc[mt][nt], ah[fb][mt], pl);
                MMA16816(acc[mt][nt], al[fb][mt], ph);
            }
    };

    load_stage(0, 0);
    load_stage(1, 1);
    load_stage(2, 2);
    CPA_WAIT1();                 // stages 0,1 resident
    __syncthreads();
    ldfrags(0, 0, smb);          // stage 0, sub 0, kk 0

    for (int s = 0; s < S; ++s) {
        uint32_t sb = smb + (s % 3) * 65536;

        ldfrags(1, 1, sb);                 // sub0 kk1
        do_mma(0);
        ldfrags(0, 0, sb + 32768);         // sub1 kk0
        do_mma(1);
        ldfrags(1, 1, sb + 32768);         // sub1 kk1
        do_mma(0);

        CPA_WAIT1();                       // stage s+1 resident
        if (s + 1 < S)
            ldfrags(0, 0, smb + ((s + 1) % 3) * 65536);  // next stage sub0 kk0
        do_mma(1);
        __syncthreads();                   // all warps done reading buf s%3

        if (s + 3 < S) load_stage(s + 3, (s + 3) % 3);
        else CPA_COMMIT();                 // keep group arithmetic
    }

    // ---- epilogue ----
    #pragma unroll
    for (int mt = 0; mt < 2; ++mt) {
        #pragma unroll
        for (int nt = 0; nt < 4; ++nt) {
            int col = colBase + warp_n * 32 + nt * 8 + (lane & 3) * 2;
            int row0 = rowBase + warp_m * 32 + mt * 16 + (lane >> 2);
            #pragma unroll
            for (int half = 0; half < 2; ++half) {
                size_t row = (size_t)(row0 + half * 8);
                float v0 = acc[mt][nt][half * 2 + 0];
                float v1 = acc[mt][nt][half * 2 + 1];
                if (flags & FLAG_BIAS) { v0 += bias[col]; v1 += bias[col + 1]; }
                if (flags & FLAG_GELU) {
                    v0 = 0.5f * v0 * (1.0f + erff(v0 * 0.70710678118654752f));
                    v1 = 0.5f * v1 * (1.0f + erff(v1 * 0.70710678118654752f));
                }
                if (flags & FLAG_RES) {
                    float2 rv = *(const float2*)(res + row * N + col);
                    v0 += rv.x; v1 += rv.y;
                }
                if (flags & FLAG_OSPL) {
                    float h0 = __bfloat162float(__float2bfloat16(v0));
                    float h1 = __bfloat162float(__float2bfloat16(v1));
                    *(uint32_t*)(Oh + row * N + col) = pack_bf2(v0, v1);
                    *(uint32_t*)(Ol + row * N + col) = pack_bf2(v0 - h0, v1 - h1);
                } else {
                    *(float2*)(C + row * N + col) = make_float2(v0, v1);
                }
            }
        }
    }
}

// =================== flash attention (conflict-free K reads) =================
#define FA_SMEM (4 * 64 * 68 * 4)
#define QKVS 3072

__global__ __launch_bounds__(128) void fattn_kernel(
    const float* __restrict__ qkv, bf16* __restrict__ oh, bf16* __restrict__ ol) {
    extern __shared__ float smf[];
    float* Qs = smf;
    float* Ks = smf + 64 * 68;
    float* Vs = smf + 2 * 64 * 68;
    float* Ps = smf + 3 * 64 * 68;

    int qt = gridDim.x - 1 - blockIdx.x;
    int bh = blockIdx.y;
    int b = bh >> 4, h = bh & 15;
    size_t base = (size_t)(b * SEQ) * QKVS + h * HD;
    int qBase = qt * 64;
    int tid = threadIdx.x;
    int ty = tid >> 3, tx = tid & 7;

    #pragma unroll
    for (int j = 0; j < 8; ++j) {
        int f = tid + j * 128;
        int rr = f >> 4, d4 = f & 15;
        *(float4*)(Qs + rr * 68 + d4 * 4) =
            *(const float4*)(qkv + base + (size_t)(qBase + rr) * QKVS + d4 * 4);
    }

    float m[4], l[4], acc[4][8];
    #pragma unroll
    for (int i = 0; i < 4; ++i) {
        m[i] = -1e30f; l[i] = 0.0f;
        #pragma unroll
        for (int j = 0; j < 8; ++j) acc[i][j] = 0.0f;
    }

    for (int kt = 0; kt <= qt; ++kt) {
        int kBase = kt * 64;
        __syncthreads();
        #pragma unroll
        for (int j = 0; j < 8; ++j) {
            int f = tid + j * 128;
            int rr = f >> 4, d4 = f & 15;
            *(float4*)(Ks + rr * 68 + d4 * 4) =
                *(const float4*)(qkv + base + 1024 + (size_t)(kBase + rr) * QKVS + d4 * 4);
            *(float4*)(Vs + rr * 68 + d4 * 4) =
                *(const float4*)(qkv + base + 2048 + (size_t)(kBase + rr) * QKVS + d4 * 4);
        }
        __syncthreads();

        float s[4][8];
        #pragma unroll
        for (int i = 0; i < 4; ++i)
            #pragma unroll
            for (int j = 0; j < 8; ++j) s[i][j] = 0.0f;

        #pragma unroll
        for (int d4 = 0; d4 < 16; ++d4) {
            float4 qv[4];
            #pragma unroll
            for (int i = 0; i < 4; ++i)
                qv[i] = *(const float4*)(Qs + (ty + 16 * i) * 68 + d4 * 4);
            #pragma unroll
            for (int j = 0; j < 8; ++j) {
                float4 kv = *(const float4*)(Ks + (j * 8 + tx) * 68 + d4 * 4);
                #pragma unroll
                for (int i = 0; i < 4; ++i) {
                    s[i][j] = fmaf(qv[i].x, kv.x, s[i][j]);
                    s[i][j] = fmaf(qv[i].y, kv.y, s[i][j]);
                    s[i][j] = fmaf(qv[i].z, kv.z, s[i][j]);
                    s[i][j] = fmaf(qv[i].w, kv.w, s[i][j]);
                }
            }
        }

        bool diag = (kt == qt);
        #pragma unroll
        for (int i = 0; i < 4; ++i) {
            int R = ty + 16 * i;
            float mx = -1e30f;
            #pragma unroll
            for (int j = 0; j < 8; ++j) {
                float sv = s[i][j] * 0.125f;
                if (diag && (j * 8 + tx > R)) sv = -1e30f;
                s[i][j] = sv;
                mx = fmaxf(mx, sv);
            }
            mx = fmaxf(mx, __shfl_xor_sync(0xffffffffu, mx, 1));
            mx = fmaxf(mx, __shfl_xor_sync(0xffffffffu, mx, 2));
            mx = fmaxf(mx, __shfl_xor_sync(0xffffffffu, mx, 4));
            float mnew = fmaxf(m[i], mx);
            float corr = __expf(m[i] - mnew);
            float psum = 0.0f;
            #pragma unroll
            for (int j = 0; j < 8; ++j) {
                float p = __expf(s[i][j] - mnew);
                Ps[R * 68 + j * 8 + tx] = p;
                psum += p;
            }
            psum += __shfl_xor_sync(0xffffffffu, psum, 1);
            psum += __shfl_xor_sync(0xffffffffu, psum, 2);
            psum += __shfl_xor_sync(0xffffffffu, psum, 4);
            l[i] = l[i] * corr + psum;
            m[i] = mnew;
            #pragma unroll
            for (int j = 0; j < 8; ++j) acc[i][j] *= corr;
        }
        __syncwarp();

        #pragma unroll
        for (int s4 = 0; s4 < 16; ++s4) {
            float4 pv[4];
            #pragma unroll
            for (int i = 0; i < 4; ++i)
                pv[i] = *(const float4*)(Ps + (ty + 16 * i) * 68 + s4 * 4);
            #pragma unroll
            for (int ss = 0; ss < 4; ++ss) {
                const float* vr = Vs + (s4 * 4 + ss) * 68 + tx * 8;
                float4 v0 = *(const float4*)(vr);
                float4 v1 = *(const float4*)(vr + 4);
                #pragma unroll
                for (int i = 0; i < 4; ++i) {
                    float p = (ss == 0) ? pv[i].x : (ss == 1) ? pv[i].y :
                              (ss == 2) ? pv[i].z : pv[i].w;
                    acc[i][0] = fmaf(p, v0.x, acc[i][0]);
                    acc[i][1] = fmaf(p, v0.y, acc[i][1]);
                    acc[i][2] = fmaf(p, v0.z, acc[i][2]);
                    acc[i][3] = fmaf(p, v0.w, acc[i][3]);
                    acc[i][4] = fmaf(p, v1.x, acc[i][4]);
                    acc[i][5] = fmaf(p, v1.y, acc[i][5]);
                    acc[i][6] = fmaf(p, v1.z, acc[i][6]);
                    acc[i][7] = fmaf(p, v1.w, acc[i][7]);
                }
            }
        }
        __syncwarp();
    }

    #pragma unroll
    for (int i = 0; i < 4; ++i) {
        float inv = 1.0f / l[i];
        size_t off = (size_t)(b * SEQ + qBase + ty + 16 * i) * EMB + h * HD + tx * 8;
        #pragma unroll
        for (int j = 0; j < 8; j += 2) {
            float v0 = acc[i][j] * inv, v1 = acc[i][j + 1] * inv;
            float h0 = __bfloat162float(__float2bfloat16(v0));
            float h1 = __bfloat162float(__float2bfloat16(v1));
            *(uint32_t*)(oh + off + j) = pack_bf2(v0, v1);
            *(uint32_t*)(ol + off + j) = pack_bf2(v0 - h0, v1 - h1);
        }
    }
}

// ---------------- launch ----------------------------------------------------
extern "C" void kernel_launch(void* const* d_in, const int* in_sizes, int n_in,
                              void* d_out, int out_size) {
    const int*   idx    = (const int*)d_in[0];
    const float* tok    = (const float*)d_in[1];
    const float* pos    = (const float*)d_in[2];
    const float* Wq     = (const float*)d_in[3];
    const float* Wk     = (const float*)d_in[4];
    const float* Wv     = (const float*)d_in[5];
    const float* Wp     = (const float*)d_in[6];
    const float* bp     = (const float*)d_in[7];
    const float* ln1_g  = (const float*)d_in[8];
    const float* ln1_b  = (const float*)d_in[9];
    const float* ln2_g  = (const float*)d_in[10];
    const float* ln2_b  = (const float*)d_in[11];
    const float* W1     = (const float*)d_in[12];
    const float* b1     = (const float*)d_in[13];
    const float* W2     = (const float*)d_in[14];
    const float* b2     = (const float*)d_in[15];
    const float* lnf_g  = (const float*)d_in[16];
    const float* lnf_b  = (const float*)d_in[17];
    const float* Wout   = (const float*)d_in[18];

    float *x, *qkv;
    bf16 *hh, *hl, *ohh, *ohl, *uh, *ul;
    bf16 *wqkvh, *wqkvl, *wph, *wpl, *w1h, *w1l, *w2h, *w2l, *woh, *wol;
    cudaGetSymbolAddress((void**)&x, g_x);
    cudaGetSymbolAddress((void**)&qkv, g_qkv);
    cudaGetSymbolAddress((void**)&hh, g_h_h);
    cudaGetSymbolAddress((void**)&hl, g_h_l);
    cudaGetSymbolAddress((void**)&ohh, g_o_h);
    cudaGetSymbolAddress((void**)&ohl, g_o_l);
    cudaGetSymbolAddress((void**)&uh, g_u_h);
    cudaGetSymbolAddress((void**)&ul, g_u_l);
    cudaGetSymbolAddress((void**)&wqkvh, g_Wqkv_h); cudaGetSymbolAddress((void**)&wqkvl, g_Wqkv_l);
    cudaGetSymbolAddress((void**)&wph, g_Wp_h);     cudaGetSymbolAddress((void**)&wpl, g_Wp_l);
    cudaGetSymbolAddress((void**)&w1h, g_W1_h);     cudaGetSymbolAddress((void**)&w1l, g_W1_l);
    cudaGetSymbolAddress((void**)&w2h, g_W2_h);     cudaGetSymbolAddress((void**)&w2l, g_W2_l);
    cudaGetSymbolAddress((void**)&woh, g_Wo_h);     cudaGetSymbolAddress((void**)&wol, g_Wo_l);

    cudaFuncSetAttribute(mgemm7_kernel, cudaFuncAttributeMaxDynamicSharedMemorySize, MG_SMEM);
    cudaFuncSetAttribute(fattn_kernel, cudaFuncAttributeMaxDynamicSharedMemorySize, FA_SMEM);

    tconv_all<<<130304, dim3(32, 8)>>>(Wq, Wk, Wv, Wp, W1, W2, Wout,
                                       wqkvh, wqkvl, wph, wpl, w1h, w1l,
                                       w2h, w2l, woh, wol);
    embed_kernel<<<NTOK, 256>>>(idx, tok, pos, x);

    dim3 gQKV(NTOK / 128, 3 * EMB / 128);
    dim3 gE(NTOK / 128, EMB / 128);
    dim3 gH(NTOK / 128, HID / 128);
    dim3 gV(NTOK / 128, VOCAB / 128);
    dim3 gA(SEQ / 64, 2 * NH);

    for (int l = 0; l < NL; l++) {
        size_t wo = (size_t)l * EMB * EMB;
        size_t wqo = (size_t)l * 3 * EMB * EMB;
        size_t w1o = (size_t)l * EMB * HID;

        ln_kernel<<<NTOK, 256>>>(x, ln1_g + l * EMB, ln1_b + l * EMB, hh, hl);
        mgemm7_kernel<<<gQKV, 512, MG_SMEM>>>(hh, hl, wqkvh + wqo, wqkvl + wqo,
                                              nullptr, nullptr, qkv, nullptr, nullptr,
                                              NTOK, 3 * EMB, EMB, 0);
        fattn_kernel<<<gA, 128, FA_SMEM>>>(qkv, ohh, ohl);
        mgemm7_kernel<<<gE, 512, MG_SMEM>>>(ohh, ohl, wph + wo, wpl + wo, bp + l * EMB, x,
                                            x, nullptr, nullptr, NTOK, EMB, EMB,
                                            FLAG_BIAS | FLAG_RES);
        ln_kernel<<<NTOK, 256>>>(x, ln2_g + l * EMB, ln2_b + l * EMB, hh, hl);
        mgemm7_kernel<<<gH, 512, MG_SMEM>>>(hh, hl, w1h + w1o, w1l + w1o, b1 + l * HID,
                                            nullptr, nullptr, uh, ul, NTOK, HID, EMB,
                                            FLAG_BIAS | FLAG_GELU | FLAG_OSPL);
        mgemm7_kernel<<<gE, 512, MG_SMEM>>>(uh, ul, w2h + w1o, w2l + w1o, b2 + l * EMB, x,
                                            x, nullptr, nullptr, NTOK, EMB, HID,
                                            FLAG_BIAS | FLAG_RES);
    }

    ln_kernel<<<NTOK, 256>>>(x, lnf_g, lnf_b, hh, hl);
    mgemm7_kernel<<<gV, 512, MG_SMEM>>>(hh, hl, woh, wol, nullptr, nullptr,
                                        (float*)d_out, nullptr, nullptr,
                                        NTOK, VOCAB, EMB, 0);
}

// round 11
// speedup vs baseline: 1.4201x; 1.4201x over previous
#include <cuda_runtime.h>
#include <cuda_bf16.h>
#include <math.h>
#include <stdint.h>

#define NTOK 4096
#define EMB  1024
#define HID  4096
#define VOCAB 32000
#define SEQ  2048
#define NH   16
#define HD   64
#define NL   8

typedef __nv_bfloat16 bf16;
typedef __nv_bfloat162 bf162;

// ---------------- device scratch --------------------------------------------
__device__ __align__(16) float g_x[NTOK * EMB];

__device__ __align__(16) bf16 g_h_h[NTOK * EMB];
__device__ __align__(16) bf16 g_h_l[NTOK * EMB];
__device__ __align__(16) bf16 g_qkv_h[NTOK * 3 * EMB];
__device__ __align__(16) bf16 g_qkv_l[NTOK * 3 * EMB];
__device__ __align__(16) bf16 g_o_h[NTOK * EMB];
__device__ __align__(16) bf16 g_o_l[NTOK * EMB];
__device__ __align__(16) bf16 g_u_h[NTOK * HID];
__device__ __align__(16) bf16 g_u_l[NTOK * HID];

// transposed weights [N][K] hi/lo; QKV fused to [3E][E] per layer
__device__ __align__(16) bf16 g_Wqkv_h[NL * 3 * EMB * EMB];
__device__ __align__(16) bf16 g_Wqkv_l[NL * 3 * EMB * EMB];
__device__ __align__(16) bf16 g_Wp_h[NL * EMB * EMB];
__device__ __align__(16) bf16 g_Wp_l[NL * EMB * EMB];
__device__ __align__(16) bf16 g_W1_h[NL * EMB * HID];
__device__ __align__(16) bf16 g_W1_l[NL * EMB * HID];
__device__ __align__(16) bf16 g_W2_h[NL * EMB * HID];
__device__ __align__(16) bf16 g_W2_l[NL * EMB * HID];
__device__ __align__(16) bf16 g_Wo_h[(size_t)VOCAB * EMB];
__device__ __align__(16) bf16 g_Wo_l[(size_t)VOCAB * EMB];

// ---------------- helpers ---------------------------------------------------
__device__ __forceinline__ uint32_t smem_u32(const void* p) {
    return (uint32_t)__cvta_generic_to_shared((void*)p);
}
__device__ __forceinline__ uint32_t pack_bf2(float a, float b) {
    bf162 t = __floats2bfloat162_rn(a, b);
    return *reinterpret_cast<uint32_t*>(&t);
}
__device__ __forceinline__ void cpa16(uint32_t dst, const void* src) {
    asm volatile("cp.async.ca.shared.global [%0], [%1], 16;" :: "r"(dst), "l"(src));
}
#define CPA_COMMIT() asm volatile("cp.async.commit_group;" ::: "memory")
#define CPA_WAIT1()  asm volatile("cp.async.wait_group 1;" ::: "memory")
#define CPA_WAIT0()  asm volatile("cp.async.wait_group 0;" ::: "memory")

#define LDSM4(r, a) \
    asm volatile("ldmatrix.sync.aligned.m8n8.x4.shared.b16 {%0,%1,%2,%3}, [%4];" \
        : "=r"((r)[0]), "=r"((r)[1]), "=r"((r)[2]), "=r"((r)[3]) : "r"(a))

#define LDSM4T(r, a) \
    asm volatile("ldmatrix.sync.aligned.m8n8.x4.trans.shared.b16 {%0,%1,%2,%3}, [%4];" \
        : "=r"((r)[0]), "=r"((r)[1]), "=r"((r)[2]), "=r"((r)[3]) : "r"(a))

#define MMA16816(d, a, b) \
    asm volatile("mma.sync.aligned.m16n8k16.row.col.f32.bf16.bf16.f32 " \
        "{%0,%1,%2,%3},{%4,%5,%6,%7},{%8,%9},{%0,%1,%2,%3};" \
        : "+f"((d)[0]), "+f"((d)[1]), "+f"((d)[2]), "+f"((d)[3]) \
        : "r"((a)[0]), "r"((a)[1]), "r"((a)[2]), "r"((a)[3]), \
          "r"((b)[0]), "r"((b)[1]))

// ---------------- all-weights transpose + split-convert ----------------------
__global__ void tconv_all(const float* __restrict__ Wq, const float* __restrict__ Wk,
                          const float* __restrict__ Wv, const float* __restrict__ Wp,
                          const float* __restrict__ W1, const float* __restrict__ W2,
                          const float* __restrict__ Wout,
                          bf16* __restrict__ qkvh, bf16* __restrict__ qkvl,
                          bf16* __restrict__ wph, bf16* __restrict__ wpl,
                          bf16* __restrict__ w1h, bf16* __restrict__ w1l,
                          bf16* __restrict__ w2h, bf16* __restrict__ w2l,
                          bf16* __restrict__ woh, bf16* __restrict__ wol) {
    __shared__ float t[32][33];
    int b = blockIdx.x;
    const float* src; bf16 *oh, *ol;
    int K, N, tilesX, tloc, rowOff = 0;

    if (b < 24576) {
        int type = b / 8192, lb = b % 8192;
        int layer = lb / 1024; tloc = lb % 1024;
        K = 1024; N = 1024; tilesX = 32;
        src = (type == 0 ? Wq : type == 1 ? Wk : Wv) + (size_t)layer * EMB * EMB;
        oh = qkvh + (size_t)layer * 3 * EMB * EMB;
        ol = qkvl + (size_t)layer * 3 * EMB * EMB;
        rowOff = type * 1024;
    } else if (b < 32768) {
        int lb = b - 24576;
        int layer = lb / 1024; tloc = lb % 1024;
        K = 1024; N = 1024; tilesX = 32;
        src = Wp + (size_t)layer * EMB * EMB;
        oh = wph + (size_t)layer * EMB * EMB;
        ol = wpl + (size_t)layer * EMB * EMB;
    } else if (b < 65536) {
        int lb = b - 32768;
        int layer = lb / 4096; tloc = lb % 4096;
        K = 1024; N = 4096; tilesX = 128;
        src = W1 + (size_t)layer * EMB * HID;
        oh = w1h + (size_t)layer * EMB * HID;
        ol = w1l + (size_t)layer * EMB * HID;
    } else if (b < 98304) {
        int lb = b - 65536;
        int layer = lb / 4096; tloc = lb % 4096;
        K = 4096; N = 1024; tilesX = 32;
        src = W2 + (size_t)layer * HID * EMB;
        oh = w2h + (size_t)layer * HID * EMB;
        ol = w2l + (size_t)layer * HID * EMB;
    } else {
        tloc = b - 98304;
        K = 1024; N = VOCAB; tilesX = 1000;
        src = Wout; oh = woh; ol = wol;
    }

    int bx = (tloc % tilesX) * 32;
    int by = (tloc / tilesX) * 32;
    int x = threadIdx.x, y = threadIdx.y;
    #pragma unroll
    for (int i = 0; i < 4; i++)
        t[y + i * 8][x] = src[(size_t)(by + y + i * 8) * N + bx + x];
    __syncthreads();
    #pragma unroll
    for (int i = 0; i < 4; i++) {
        int n = bx + y + i * 8, k = by + x;
        float v = t[x][y + i * 8];
        bf16 hv = __float2bfloat16(v);
        oh[(size_t)(rowOff + n) * K + k] = hv;
        ol[(size_t)(rowOff + n) * K + k] = __float2bfloat16(v - __bfloat162float(hv));
    }
}

// ---------------- embed ------------------------------------------------------
__global__ void embed_kernel(const int* __restrict__ idx, const float* __restrict__ tok,
                             const float* __restrict__ pos, float* __restrict__ x) {
    int n = blockIdx.x, e4 = threadIdx.x, t = n & (SEQ - 1);
    float4 a = ((const float4*)(tok + (size_t)idx[n] * EMB))[e4];
    float4 b = ((const float4*)(pos + (size_t)t * EMB))[e4];
    a.x += b.x; a.y += b.y; a.z += b.z; a.w += b.w;
    ((float4*)(x + (size_t)n * EMB))[e4] = a;
}

// ---------------- layernorm -> hi/lo bf16 ------------------------------------
__device__ __forceinline__ float block_sum_256(float s, float* red) {
    #pragma unroll
    for (int o = 16; o; o >>= 1) s += __shfl_xor_sync(0xffffffffu, s, o);
    if ((threadIdx.x & 31) == 0) red[threadIdx.x >> 5] = s;
    __syncthreads();
    if (threadIdx.x < 32) {
        float t = (threadIdx.x < 8) ? red[threadIdx.x] : 0.0f;
        #pragma unroll
        for (int o = 4; o; o >>= 1) t += __shfl_xor_sync(0xffffffffu, t, o);
        if (threadIdx.x == 0) red[0] = t;
    }
    __syncthreads();
    float r = red[0];
    __syncthreads();
    return r;
}

__global__ void ln_kernel(const float* __restrict__ x, const float* __restrict__ g,
                          const float* __restrict__ b, bf16* __restrict__ oh,
                          bf16* __restrict__ ol) {
    __shared__ float red[8];
    int n = blockIdx.x, tid = threadIdx.x;
    float4 v = ((const float4*)(x + (size_t)n * EMB))[tid];
    float mu = block_sum_256(v.x + v.y + v.z + v.w, red) * (1.0f / EMB);
    float dx = v.x - mu, dy = v.y - mu, dz = v.z - mu, dw = v.w - mu;
    float var = block_sum_256(dx*dx + dy*dy + dz*dz + dw*dw, red) * (1.0f / EMB);
    float rs = rsqrtf(var + 1e-5f);
    float4 gg = ((const float4*)g)[tid];
    float4 bb = ((const float4*)b)[tid];
    float r0 = dx*rs*gg.x + bb.x, r1 = dy*rs*gg.y + bb.y;
    float r2 = dz*rs*gg.z + bb.z, r3 = dw*rs*gg.w + bb.w;
    float h0 = __bfloat162float(__float2bfloat16(r0));
    float h1 = __bfloat162float(__float2bfloat16(r1));
    float h2 = __bfloat162float(__float2bfloat16(r2));
    float h3 = __bfloat162float(__float2bfloat16(r3));
    size_t o = (size_t)n * EMB + tid * 4;
    *(uint2*)(oh + o) = make_uint2(pack_bf2(r0, r1), pack_bf2(r2, r3));
    *(uint2*)(ol + o) = make_uint2(pack_bf2(r0 - h0, r1 - h1), pack_bf2(r2 - h2, r3 - h3));
}

// ============= 16-warp cross-stage-pipelined split-bf16 MMA GEMM =============
// (exact mgemm6 from R9 — best measured GEMM)
#define FLAG_BIAS 1
#define FLAG_GELU 2
#define FLAG_RES  4
#define FLAG_OSPL 8
#define MG_SMEM (4 * 32768)

__global__ __launch_bounds__(512, 1) void mgemm6_kernel(
    const bf16* __restrict__ Ah, const bf16* __restrict__ Al,
    const bf16* __restrict__ Bh, const bf16* __restrict__ Bl,
    const float* __restrict__ bias, const float* __restrict__ res,
    float* __restrict__ C, bf16* __restrict__ Oh, bf16* __restrict__ Ol,
    int M, int N, int K, int flags) {
    extern __shared__ char sm[];
    uint32_t smb = smem_u32(sm);

    int tid = threadIdx.x;
    int lane = tid & 31, wid = tid >> 5;
    int warp_m = wid >> 2, warp_n = wid & 3;
    int rowBase = blockIdx.x * 128, colBase = blockIdx.y * 128;

    float acc[2][4][4];
    #pragma unroll
    for (int i = 0; i < 2; i++)
        #pragma unroll
        for (int j = 0; j < 4; j++)
            #pragma unroll
            for (int q = 0; q < 4; q++) acc[i][j][q] = 0.0f;

    uint32_t offA[2][2][2], offB[2][2][2];
    #pragma unroll
    for (int kk = 0; kk < 2; ++kk) {
        #pragma unroll
        for (int mt = 0; mt < 2; ++mt) {
            int r = warp_m * 32 + mt * 16 + (lane & 15);
            int ch = kk * 2 + (lane >> 4);
            offA[kk][mt][0] = (uint32_t)(r * 128 + ((ch ^ (r & 7)) * 16));
            offA[kk][mt][1] = (uint32_t)(r * 128 + (((ch + 4) ^ (r & 7)) * 16));
        }
        #pragma unroll
        for (int g2 = 0; g2 < 2; ++g2) {
            int n = warp_n * 32 + g2 * 16 + ((lane >> 4) << 3) + (lane & 7);
            int ch = kk * 2 + ((lane >> 3) & 1);
            offB[kk][g2][0] = (uint32_t)(16384 + n * 128 + ((ch ^ (n & 7)) * 16));
            offB[kk][g2][1] = (uint32_t)(16384 + n * 128 + (((ch + 4) ^ (n & 7)) * 16));
        }
    }

    int S = K >> 5;

    auto load_stage = [&](int s, int buf) {
        uint32_t sb = smb + buf * 32768;
        const bf16* gAh = Ah + (size_t)rowBase * K + s * 32;
        const bf16* gAl = Al + (size_t)rowBase * K + s * 32;
        const bf16* gBh = Bh + (size_t)colBase * K + s * 32;
        const bf16* gBl = Bl + (size_t)colBase * K + s * 32;
        #pragma unroll
        for (int i = 0; i < 2; i++) {
            int f = tid + i * 512;
            int r = f >> 3, c = f & 7;
            uint32_t so = (uint32_t)(r * 128 + ((c ^ (r & 7)) * 16));
            const bf16* srcA = (c < 4) ? (gAh + (size_t)r * K + c * 8)
                                       : (gAl + (size_t)r * K + (c - 4) * 8);
            const bf16* srcB = (c < 4) ? (gBh + (size_t)r * K + c * 8)
                                       : (gBl + (size_t)r * K + (c - 4) * 8);
            cpa16(sb + so, srcA);
            cpa16(sb + 16384 + so, srcB);
        }
        CPA_COMMIT();
    };

    uint32_t ah[2][2][4], al[2][2][4], bh[2][8], bl[2][8];

    auto ldfrags = [&](int fb, int kk, uint32_t sb) {
        #pragma unroll
        for (int mt = 0; mt < 2; ++mt) {
            LDSM4(ah[fb][mt], sb + offA[kk][mt][0]);
            LDSM4(al[fb][mt], sb + offA[kk][mt][1]);
        }
        #pragma unroll
        for (int g2 = 0; g2 < 2; ++g2) {
            LDSM4(&bh[fb][g2 * 4], sb + offB[kk][g2][0]);
            LDSM4(&bl[fb][g2 * 4], sb + offB[kk][g2][1]);
        }
    };

    auto do_mma = [&](int fb) {
        #pragma unroll
        for (int mt = 0; mt < 2; ++mt)
            #pragma unroll
            for (int nt = 0; nt < 4; ++nt) {
                uint32_t* ph = &bh[fb][(nt >> 1) * 4 + (nt & 1) * 2];
                uint32_t* pl = &bl[fb][(nt >> 1) * 4 + (nt & 1) * 2];
                MMA16816(acc[mt][nt], ah[fb][mt], ph);
                MMA16816(acc[mt][nt], ah[fb][mt], pl);
                MMA16816(acc[mt][nt], al[fb][mt], ph);
            }
    };

    load_stage(0, 0);
    load_stage(1, 1);
    load_stage(2, 2);
    CPA_WAIT1();
    __syncthreads();
    ldfrags(0, 0, smb);

    for (int s = 0; s < S; ++s) {
        uint32_t sb = smb + (s & 3) * 32768;

        if (s + 3 < S) load_stage(s + 3, (s + 3) & 3);
        else CPA_COMMIT();

        ldfrags(1, 1, sb);
        do_mma(0);

        CPA_WAIT1();
        if (s + 1 < S)
            ldfrags(0, 0, smb + ((s + 1) & 3) * 32768);
        do_mma(1);
        __syncthreads();
    }

    #pragma unroll
    for (int mt = 0; mt < 2; ++mt) {
        #pragma unroll
        for (int nt = 0; nt < 4; ++nt) {
            int col = colBase + warp_n * 32 + nt * 8 + (lane & 3) * 2;
            int row0 = rowBase + warp_m * 32 + mt * 16 + (lane >> 2);
            #pragma unroll
            for (int half = 0; half < 2; ++half) {
                size_t row = (size_t)(row0 + half * 8);
                float v0 = acc[mt][nt][half * 2 + 0];
                float v1 = acc[mt][nt][half * 2 + 1];
                if (flags & FLAG_BIAS) { v0 += bias[col]; v1 += bias[col + 1]; }
                if (flags & FLAG_GELU) {
                    v0 = 0.5f * v0 * (1.0f + erff(v0 * 0.70710678118654752f));
                    v1 = 0.5f * v1 * (1.0f + erff(v1 * 0.70710678118654752f));
                }
                if (flags & FLAG_RES) {
                    float2 rv = *(const float2*)(res + row * N + col);
                    v0 += rv.x; v1 += rv.y;
                }
                if (flags & FLAG_OSPL) {
                    float h0 = __bfloat162float(__float2bfloat16(v0));
                    float h1 = __bfloat162float(__float2bfloat16(v1));
                    *(uint32_t*)(Oh + row * N + col) = pack_bf2(v0, v1);
                    *(uint32_t*)(Ol + row * N + col) = pack_bf2(v0 - h0, v1 - h1);
                } else {
                    *(float2*)(C + row * N + col) = make_float2(v0, v1);
                }
            }
        }
    }
}

// ============== MMA flash attention (split-bf16, 4 warps, 64-q tile) =========
// qkv hi/lo: [NTOK][3072]. smem: Qh Ql Kh Kl Vh Vl, each 64 rows x 128B swizzled.
#define FA_SMEM 49152
#define QKVS 3072

__global__ __launch_bounds__(128) void mattn_kernel(
    const bf16* __restrict__ qkvh, const bf16* __restrict__ qkvl,
    bf16* __restrict__ oh, bf16* __restrict__ ol) {
    extern __shared__ char smc[];
    uint32_t smb = smem_u32(smc);
    uint32_t Qh = smb, Ql = smb + 8192;
    uint32_t Kh = smb + 16384, Kl = smb + 24576;
    uint32_t Vh = smb + 32768, Vl = smb + 40960;

    int qt = gridDim.x - 1 - blockIdx.x;   // long blocks first
    int bh = blockIdx.y;
    int b = bh >> 4, h = bh & 15;
    int tid = threadIdx.x, lane = tid & 31, w = tid >> 5;
    int qBase = qt * 64;
    size_t rowQ = (size_t)(b * SEQ + qBase);

    // stage Q (hi/lo)
    #pragma unroll
    for (int i = 0; i < 4; ++i) {
        int f = tid + i * 128;
        int r = f >> 3, c = f & 7;
        uint32_t so = (uint32_t)(r * 128 + ((c ^ (r & 7)) * 16));
        size_t g = (rowQ + r) * QKVS + h * HD + c * 8;
        cpa16(Qh + so, qkvh + g);
        cpa16(Ql + so, qkvl + g);
    }
    CPA_COMMIT();

    float m0 = -1e30f, m1 = -1e30f, l0 = 0.0f, l1 = 0.0f;
    float oacc[8][4];
    #pragma unroll
    for (int nt = 0; nt < 8; ++nt)
        #pragma unroll
        for (int e = 0; e < 4; ++e) oacc[nt][e] = 0.0f;

    int r0g = qBase + w * 16 + (lane >> 2);    // global q row (half 0)

    for (int kt = 0; kt <= qt; ++kt) {
        int kBase = kt * 64;
        size_t rowK = (size_t)(b * SEQ + kBase);
        __syncthreads();                        // prior K/V reads done
        #pragma unroll
        for (int i = 0; i < 4; ++i) {
            int f = tid + i * 128;
            int r = f >> 3, c = f & 7;
            uint32_t so = (uint32_t)(r * 128 + ((c ^ (r & 7)) * 16));
            size_t gk = (rowK + r) * QKVS + 1024 + h * HD + c * 8;
            cpa16(Kh + so, qkvh + gk);
            cpa16(Kl + so, qkvl + gk);
            cpa16(Vh + so, qkvh + gk + 1024);
            cpa16(Vl + so, qkvl + gk + 1024);
        }
        CPA_COMMIT();
        CPA_WAIT0();
        __syncthreads();

        // ---- QK^T: sacc[8 ntiles][4] ----
        float sacc[8][4];
        #pragma unroll
        for (int nt = 0; nt < 8; ++nt)
            #pragma unroll
            for (int e = 0; e < 4; ++e) sacc[nt][e] = 0.0f;

        #pragma unroll
        for (int kk = 0; kk < 4; ++kk) {        // d slices of 16
            uint32_t aq[4], aql[4];
            {
                int r = w * 16 + (lane & 15);
                int ch = kk * 2 + (lane >> 4);
                uint32_t so = (uint32_t)(r * 128 + ((ch ^ (r & 7)) * 16));
                LDSM4(aq, Qh + so);
                LDSM4(aql, Ql + so);
            }
            #pragma unroll
            for (int g2 = 0; g2 < 4; ++g2) {    // s groups of 16
                int n = g2 * 16 + ((lane >> 4) << 3) + (lane & 7);
                int ch = kk * 2 + ((lane >> 3) & 1);
                uint32_t so = (uint32_t)(n * 128 + ((ch ^ (n & 7)) * 16));
                uint32_t bk[4], bkl[4];
                LDSM4(bk, Kh + so);
                LDSM4(bkl, Kl + so);
                MMA16816(sacc[g2*2],     aq,  &bk[0]);
                MMA16816(sacc[g2*2],     aq,  &bkl[0]);
                MMA16816(sacc[g2*2],     aql, &bk[0]);
                MMA16816(sacc[g2*2 + 1], aq,  &bk[2]);
                MMA16816(sacc[g2*2 + 1], aq,  &bkl[2]);
                MMA16816(sacc[g2*2 + 1], aql, &bk[2]);
            }
        }

        // ---- softmax (rows lane>>2 and +8) ----
        bool diag = (kt == qt);
        float mx0 = -1e30f, mx1 = -1e30f;
        #pragma unroll
        for (int nt = 0; nt < 8; ++nt) {
            int c0 = kBase + nt * 8 + (lane & 3) * 2;
            #pragma unroll
            for (int e = 0; e < 2; ++e) {
                float v0 = sacc[nt][e] * 0.125f;
                float v1 = sacc[nt][2 + e] * 0.125f;
                if (diag) {
                    if (c0 + e > r0g)     v0 = -1e30f;
                    if (c0 + e > r0g + 8) v1 = -1e30f;
                }
                sacc[nt][e] = v0; sacc[nt][2 + e] = v1;
                mx0 = fmaxf(mx0, v0); mx1 = fmaxf(mx1, v1);
            }
        }
        mx0 = fmaxf(mx0, __shfl_xor_sync(0xffffffffu, mx0, 1));
        mx0 = fmaxf(mx0, __shfl_xor_sync(0xffffffffu, mx0, 2));
        mx1 = fmaxf(mx1, __shfl_xor_sync(0xffffffffu, mx1, 1));
        mx1 = fmaxf(mx1, __shfl_xor_sync(0xffffffffu, mx1, 2));
        float mn0 = fmaxf(m0, mx0), mn1 = fmaxf(m1, mx1);
        float cr0 = __expf(m0 - mn0), cr1 = __expf(m1 - mn1);
        float ps0 = 0.0f, ps1 = 0.0f;
        uint32_t pah[4][4], pal[4][4];
        #pragma unroll
        for (int nt = 0; nt < 8; ++nt) {
            float p0 = __expf(sacc[nt][0] - mn0);
            float p1 = __expf(sacc[nt][1] - mn0);
            float p2 = __expf(sacc[nt][2] - mn1);
            float p3 = __expf(sacc[nt][3] - mn1);
            ps0 += p0 + p1; ps1 += p2 + p3;
            float h0 = __bfloat162float(__float2bfloat16(p0));
            float h1 = __bfloat162float(__float2bfloat16(p1));
            float h2 = __bfloat162float(__float2bfloat16(p2));
            float h3 = __bfloat162float(__float2bfloat16(p3));
            int t = nt >> 1, base = (nt & 1) * 2;
            pah[t][base + 0] = pack_bf2(p0, p1);
            pah[t][base + 1] = pack_bf2(p2, p3);
            pal[t][base + 0] = pack_bf2(p0 - h0, p1 - h1);
            pal[t][base + 1] = pack_bf2(p2 - h2, p3 - h3);
        }
        ps0 += __shfl_xor_sync(0xffffffffu, ps0, 1);
        ps0 += __shfl_xor_sync(0xffffffffu, ps0, 2);
        ps1 += __shfl_xor_sync(0xffffffffu, ps1, 1);
        ps1 += __shfl_xor_sync(0xffffffffu, ps1, 2);
        l0 = l0 * cr0 + ps0; m0 = mn0;
        l1 = l1 * cr1 + ps1; m1 = mn1;
        #pragma unroll
        for (int nt = 0; nt < 8; ++nt) {
            oacc[nt][0] *= cr0; oacc[nt][1] *= cr0;
            oacc[nt][2] *= cr1; oacc[nt][3] *= cr1;
        }

        // ---- PV: o[16q][64d] += P[16q][64s] V[64s][64d] (V^T via trans ldsm) --
        #pragma unroll
        for (int t = 0; t < 4; ++t) {           // s slices of 16
            #pragma unroll
            for (int g = 0; g < 4; ++g) {       // d pairs of 16
                int r = t * 16 + ((lane >> 3) & 1) * 8 + (lane & 7);
                int ch = g * 2 + (lane >> 4);
                uint32_t so = (uint32_t)(r * 128 + ((ch ^ (r & 7)) * 16));
                uint32_t vh[4], vl[4];
                LDSM4T(vh, Vh + so);
                LDSM4T(vl, Vl + so);
                MMA16816(oacc[g*2],     pah[t], &vh[0]);
                MMA16816(oacc[g*2],     pah[t], &vl[0]);
                MMA16816(oacc[g*2],     pal[t], &vh[0]);
                MMA16816(oacc[g*2 + 1], pah[t], &vh[2]);
                MMA16816(oacc[g*2 + 1], pah[t], &vl[2]);
                MMA16816(oacc[g*2 + 1], pal[t], &vh[2]);
            }
        }
    }

    // ---- epilogue: hi/lo bf16 out, stride EMB ----
    float i0 = 1.0f / l0, i1 = 1.0f / l1;
    size_t row0 = (size_t)(b * SEQ) + qBase + w * 16 + (lane >> 2);
    #pragma unroll
    for (int nt = 0; nt < 8; ++nt) {
        int col = h * HD + nt * 8 + (lane & 3) * 2;
        float v0 = oacc[nt][0] * i0, v1 = oacc[nt][1] * i0;
        float v2 = oacc[nt][2] * i1, v3 = oacc[nt][3] * i1;
        float h0 = __bfloat162float(__float2bfloat16(v0));
        float h1 = __bfloat162float(__float2bfloat16(v1));
        float h2 = __bfloat162float(__float2bfloat16(v2));
        float h3 = __bfloat162float(__float2bfloat16(v3));
        *(uint32_t*)(oh + row0 * EMB + col)       = pack_bf2(v0, v1);
        *(uint32_t*)(ol + row0 * EMB + col)       = pack_bf2(v0 - h0, v1 - h1);
        *(uint32_t*)(oh + (row0 + 8) * EMB + col) = pack_bf2(v2, v3);
        *(uint32_t*)(ol + (row0 + 8) * EMB + col) = pack_bf2(v2 - h2, v3 - h3);
    }
}

// ---------------- launch ----------------------------------------------------
extern "C" void kernel_launch(void* const* d_in, const int* in_sizes, int n_in,
                              void* d_out, int out_size) {
    const int*   idx    = (const int*)d_in[0];
    const float* tok    = (const float*)d_in[1];
    const float* pos    = (const float*)d_in[2];
    const float* Wq     = (const float*)d_in[3];
    const float* Wk     = (const float*)d_in[4];
    const float* Wv     = (const float*)d_in[5];
    const float* Wp     = (const float*)d_in[6];
    const float* bp     = (const float*)d_in[7];
    const float* ln1_g  = (const float*)d_in[8];
    const float* ln1_b  = (const float*)d_in[9];
    const float* ln2_g  = (const float*)d_in[10];
    const float* ln2_b  = (const float*)d_in[11];
    const float* W1     = (const float*)d_in[12];
    const float* b1     = (const float*)d_in[13];
    const float* W2     = (const float*)d_in[14];
    const float* b2     = (const float*)d_in[15];
    const float* lnf_g  = (const float*)d_in[16];
    const float* lnf_b  = (const float*)d_in[17];
    const float* Wout   = (const float*)d_in[18];

    float *x;
    bf16 *hh, *hl, *qkvh, *qkvl, *ohh, *ohl, *uh, *ul;
    bf16 *wqkvh, *wqkvl, *wph, *wpl, *w1h, *w1l, *w2h, *w2l, *woh, *wol;
    cudaGetSymbolAddress((void**)&x, g_x);
    cudaGetSymbolAddress((void**)&hh, g_h_h);
    cudaGetSymbolAddress((void**)&hl, g_h_l);
    cudaGetSymbolAddress((void**)&qkvh, g_qkv_h);
    cudaGetSymbolAddress((void**)&qkvl, g_qkv_l);
    cudaGetSymbolAddress((void**)&ohh, g_o_h);
    cudaGetSymbolAddress((void**)&ohl, g_o_l);
    cudaGetSymbolAddress((void**)&uh, g_u_h);
    cudaGetSymbolAddress((void**)&ul, g_u_l);
    cudaGetSymbolAddress((void**)&wqkvh, g_Wqkv_h); cudaGetSymbolAddress((void**)&wqkvl, g_Wqkv_l);
    cudaGetSymbolAddress((void**)&wph, g_Wp_h);     cudaGetSymbolAddress((void**)&wpl, g_Wp_l);
    cudaGetSymbolAddress((void**)&w1h, g_W1_h);     cudaGetSymbolAddress((void**)&w1l, g_W1_l);
    cudaGetSymbolAddress((void**)&w2h, g_W2_h);     cudaGetSymbolAddress((void**)&w2l, g_W2_l);
    cudaGetSymbolAddress((void**)&woh, g_Wo_h);     cudaGetSymbolAddress((void**)&wol, g_Wo_l);

    cudaFuncSetAttribute(mgemm6_kernel, cudaFuncAttributeMaxDynamicSharedMemorySize, MG_SMEM);
    cudaFuncSetAttribute(mattn_kernel, cudaFuncAttributeMaxDynamicSharedMemorySize, FA_SMEM);

    tconv_all<<<130304, dim3(32, 8)>>>(Wq, Wk, Wv, Wp, W1, W2, Wout,
                                       wqkvh, wqkvl, wph, wpl, w1h, w1l,
                                       w2h, w2l, woh, wol);
    embed_kernel<<<NTOK, 256>>>(idx, tok, pos, x);

    dim3 gQKV(NTOK / 128, 3 * EMB / 128);
    dim3 gE(NTOK / 128, EMB / 128);
    dim3 gH(NTOK / 128, HID / 128);
    dim3 gV(NTOK / 128, VOCAB / 128);
    dim3 gA(SEQ / 64, 2 * NH);

    for (int l = 0; l < NL; l++) {
        size_t wo = (size_t)l * EMB * EMB;
        size_t wqo = (size_t)l * 3 * EMB * EMB;
        size_t w1o = (size_t)l * EMB * HID;

        ln_kernel<<<NTOK, 256>>>(x, ln1_g + l * EMB, ln1_b + l * EMB, hh, hl);
        mgemm6_kernel<<<gQKV, 512, MG_SMEM>>>(hh, hl, wqkvh + wqo, wqkvl + wqo,
                                              nullptr, nullptr, nullptr, qkvh, qkvl,
                                              NTOK, 3 * EMB, EMB, FLAG_OSPL);
        mattn_kernel<<<gA, 128, FA_SMEM>>>(qkvh, qkvl, ohh, ohl);
        mgemm6_kernel<<<gE, 512, MG_SMEM>>>(ohh, ohl, wph + wo, wpl + wo, bp + l * EMB, x,
                                            x, nullptr, nullptr, NTOK, EMB, EMB,
                                            FLAG_BIAS | FLAG_RES);
        ln_kernel<<<NTOK, 256>>>(x, ln2_g + l * EMB, ln2_b + l * EMB, hh, hl);
        mgemm6_kernel<<<gH, 512, MG_SMEM>>>(hh, hl, w1h + w1o, w1l + w1o, b1 + l * HID,
                                            nullptr, nullptr, uh, ul, NTOK, HID, EMB,
                                            FLAG_BIAS | FLAG_GELU | FLAG_OSPL);
        mgemm6_kernel<<<gE, 512, MG_SMEM>>>(uh, ul, w2h + w1o, w2l + w1o, b2 + l * EMB, x,
                                            x, nullptr, nullptr, NTOK, EMB, HID,
                                            FLAG_BIAS | FLAG_RES);
    }

    ln_kernel<<<NTOK, 256>>>(x, lnf_g, lnf_b, hh, hl);
    mgemm6_kernel<<<gV, 512, MG_SMEM>>>(hh, hl, woh, wol, nullptr, nullptr,
                                        (float*)d_out, nullptr, nullptr,
                                        NTOK, VOCAB, EMB, 0);
}

// round 12
// speedup vs baseline: 1.4216x; 1.0011x over previous
#include <cuda_runtime.h>
#include <cuda_bf16.h>
#include <math.h>
#include <stdint.h>

#define NTOK 4096
#define EMB  1024
#define HID  4096
#define VOCAB 32000
#define SEQ  2048
#define NH   16
#define HD   64
#define NL   8

typedef __nv_bfloat16 bf16;
typedef __nv_bfloat162 bf162;

// ---------------- device scratch --------------------------------------------
__device__ __align__(16) float g_x[NTOK * EMB];

__device__ __align__(16) bf16 g_h_h[NTOK * EMB];
__device__ __align__(16) bf16 g_h_l[NTOK * EMB];
__device__ __align__(16) bf16 g_qkv_h[NTOK * 3 * EMB];
__device__ __align__(16) bf16 g_qkv_l[NTOK * 3 * EMB];
__device__ __align__(16) bf16 g_o_h[NTOK * EMB];
__device__ __align__(16) bf16 g_o_l[NTOK * EMB];
__device__ __align__(16) bf16 g_u_h[NTOK * HID];
__device__ __align__(16) bf16 g_u_l[NTOK * HID];

// transposed weights [N][K] hi/lo; QKV fused to [3E][E] per layer
__device__ __align__(16) bf16 g_Wqkv_h[NL * 3 * EMB * EMB];
__device__ __align__(16) bf16 g_Wqkv_l[NL * 3 * EMB * EMB];
__device__ __align__(16) bf16 g_Wp_h[NL * EMB * EMB];
__device__ __align__(16) bf16 g_Wp_l[NL * EMB * EMB];
__device__ __align__(16) bf16 g_W1_h[NL * EMB * HID];
__device__ __align__(16) bf16 g_W1_l[NL * EMB * HID];
__device__ __align__(16) bf16 g_W2_h[NL * EMB * HID];
__device__ __align__(16) bf16 g_W2_l[NL * EMB * HID];
__device__ __align__(16) bf16 g_Wo_h[(size_t)VOCAB * EMB];
__device__ __align__(16) bf16 g_Wo_l[(size_t)VOCAB * EMB];

// ---------------- helpers ---------------------------------------------------
__device__ __forceinline__ uint32_t smem_u32(const void* p) {
    return (uint32_t)__cvta_generic_to_shared((void*)p);
}
__device__ __forceinline__ uint32_t pack_bf2(float a, float b) {
    bf162 t = __floats2bfloat162_rn(a, b);
    return *reinterpret_cast<uint32_t*>(&t);
}
__device__ __forceinline__ void cpa16(uint32_t dst, const void* src) {
    asm volatile("cp.async.ca.shared.global [%0], [%1], 16;" :: "r"(dst), "l"(src));
}
#define CPA_COMMIT() asm volatile("cp.async.commit_group;" ::: "memory")
#define CPA_WAIT1()  asm volatile("cp.async.wait_group 1;" ::: "memory")
#define CPA_WAIT0()  asm volatile("cp.async.wait_group 0;" ::: "memory")

#define LDSM4(r, a) \
    asm volatile("ldmatrix.sync.aligned.m8n8.x4.shared.b16 {%0,%1,%2,%3}, [%4];" \
        : "=r"((r)[0]), "=r"((r)[1]), "=r"((r)[2]), "=r"((r)[3]) : "r"(a))

#define LDSM4T(r, a) \
    asm volatile("ldmatrix.sync.aligned.m8n8.x4.trans.shared.b16 {%0,%1,%2,%3}, [%4];" \
        : "=r"((r)[0]), "=r"((r)[1]), "=r"((r)[2]), "=r"((r)[3]) : "r"(a))

#define MMA16816(d, a, b) \
    asm volatile("mma.sync.aligned.m16n8k16.row.col.f32.bf16.bf16.f32 " \
        "{%0,%1,%2,%3},{%4,%5,%6,%7},{%8,%9},{%0,%1,%2,%3};" \
        : "+f"((d)[0]), "+f"((d)[1]), "+f"((d)[2]), "+f"((d)[3]) \
        : "r"((a)[0]), "r"((a)[1]), "r"((a)[2]), "r"((a)[3]), \
          "r"((b)[0]), "r"((b)[1]))

// ---------------- all-weights transpose + split-convert ----------------------
__global__ void tconv_all(const float* __restrict__ Wq, const float* __restrict__ Wk,
                          const float* __restrict__ Wv, const float* __restrict__ Wp,
                          const float* __restrict__ W1, const float* __restrict__ W2,
                          const float* __restrict__ Wout,
                          bf16* __restrict__ qkvh, bf16* __restrict__ qkvl,
                          bf16* __restrict__ wph, bf16* __restrict__ wpl,
                          bf16* __restrict__ w1h, bf16* __restrict__ w1l,
                          bf16* __restrict__ w2h, bf16* __restrict__ w2l,
                          bf16* __restrict__ woh, bf16* __restrict__ wol) {
    __shared__ float t[32][33];
    int b = blockIdx.x;
    const float* src; bf16 *oh, *ol;
    int K, N, tilesX, tloc, rowOff = 0;

    if (b < 24576) {
        int type = b / 8192, lb = b % 8192;
        int layer = lb / 1024; tloc = lb % 1024;
        K = 1024; N = 1024; tilesX = 32;
        src = (type == 0 ? Wq : type == 1 ? Wk : Wv) + (size_t)layer * EMB * EMB;
        oh = qkvh + (size_t)layer * 3 * EMB * EMB;
        ol = qkvl + (size_t)layer * 3 * EMB * EMB;
        rowOff = type * 1024;
    } else if (b < 32768) {
        int lb = b - 24576;
        int layer = lb / 1024; tloc = lb % 1024;
        K = 1024; N = 1024; tilesX = 32;
        src = Wp + (size_t)layer * EMB * EMB;
        oh = wph + (size_t)layer * EMB * EMB;
        ol = wpl + (size_t)layer * EMB * EMB;
    } else if (b < 65536) {
        int lb = b - 32768;
        int layer = lb / 4096; tloc = lb % 4096;
        K = 1024; N = 4096; tilesX = 128;
        src = W1 + (size_t)layer * EMB * HID;
        oh = w1h + (size_t)layer * EMB * HID;
        ol = w1l + (size_t)layer * EMB * HID;
    } else if (b < 98304) {
        int lb = b - 65536;
        int layer = lb / 4096; tloc = lb % 4096;
        K = 4096; N = 1024; tilesX = 32;
        src = W2 + (size_t)layer * HID * EMB;
        oh = w2h + (size_t)layer * HID * EMB;
        ol = w2l + (size_t)layer * HID * EMB;
    } else {
        tloc = b - 98304;
        K = 1024; N = VOCAB; tilesX = 1000;
        src = Wout; oh = woh; ol = wol;
    }

    int bx = (tloc % tilesX) * 32;
    int by = (tloc / tilesX) * 32;
    int x = threadIdx.x, y = threadIdx.y;
    #pragma unroll
    for (int i = 0; i < 4; i++)
        t[y + i * 8][x] = src[(size_t)(by + y + i * 8) * N + bx + x];
    __syncthreads();
    #pragma unroll
    for (int i = 0; i < 4; i++) {
        int n = bx + y + i * 8, k = by + x;
        float v = t[x][y + i * 8];
        bf16 hv = __float2bfloat16(v);
        oh[(size_t)(rowOff + n) * K + k] = hv;
        ol[(size_t)(rowOff + n) * K + k] = __float2bfloat16(v - __bfloat162float(hv));
    }
}

// ---------------- embed ------------------------------------------------------
__global__ void embed_kernel(const int* __restrict__ idx, const float* __restrict__ tok,
                             const float* __restrict__ pos, float* __restrict__ x) {
    int n = blockIdx.x, e4 = threadIdx.x, t = n & (SEQ - 1);
    float4 a = ((const float4*)(tok + (size_t)idx[n] * EMB))[e4];
    float4 b = ((const float4*)(pos + (size_t)t * EMB))[e4];
    a.x += b.x; a.y += b.y; a.z += b.z; a.w += b.w;
    ((float4*)(x + (size_t)n * EMB))[e4] = a;
}

// ---------------- layernorm -> hi/lo bf16 ------------------------------------
__device__ __forceinline__ float block_sum_256(float s, float* red) {
    #pragma unroll
    for (int o = 16; o; o >>= 1) s += __shfl_xor_sync(0xffffffffu, s, o);
    if ((threadIdx.x & 31) == 0) red[threadIdx.x >> 5] = s;
    __syncthreads();
    if (threadIdx.x < 32) {
        float t = (threadIdx.x < 8) ? red[threadIdx.x] : 0.0f;
        #pragma unroll
        for (int o = 4; o; o >>= 1) t += __shfl_xor_sync(0xffffffffu, t, o);
        if (threadIdx.x == 0) red[0] = t;
    }
    __syncthreads();
    float r = red[0];
    __syncthreads();
    return r;
}

__global__ void ln_kernel(const float* __restrict__ x, const float* __restrict__ g,
                          const float* __restrict__ b, bf16* __restrict__ oh,
                          bf16* __restrict__ ol) {
    __shared__ float red[8];
    int n = blockIdx.x, tid = threadIdx.x;
    float4 v = ((const float4*)(x + (size_t)n * EMB))[tid];
    float mu = block_sum_256(v.x + v.y + v.z + v.w, red) * (1.0f / EMB);
    float dx = v.x - mu, dy = v.y - mu, dz = v.z - mu, dw = v.w - mu;
    float var = block_sum_256(dx*dx + dy*dy + dz*dz + dw*dw, red) * (1.0f / EMB);
    float rs = rsqrtf(var + 1e-5f);
    float4 gg = ((const float4*)g)[tid];
    float4 bb = ((const float4*)b)[tid];
    float r0 = dx*rs*gg.x + bb.x, r1 = dy*rs*gg.y + bb.y;
    float r2 = dz*rs*gg.z + bb.z, r3 = dw*rs*gg.w + bb.w;
    float h0 = __bfloat162float(__float2bfloat16(r0));
    float h1 = __bfloat162float(__float2bfloat16(r1));
    float h2 = __bfloat162float(__float2bfloat16(r2));
    float h3 = __bfloat162float(__float2bfloat16(r3));
    size_t o = (size_t)n * EMB + tid * 4;
    *(uint2*)(oh + o) = make_uint2(pack_bf2(r0, r1), pack_bf2(r2, r3));
    *(uint2*)(ol + o) = make_uint2(pack_bf2(r0 - h0, r1 - h1), pack_bf2(r2 - h2, r3 - h3));
}

// ============= 16-warp cross-stage-pipelined split-bf16 MMA GEMM =============
// (exact mgemm6 from R9 — best measured GEMM)
#define FLAG_BIAS 1
#define FLAG_GELU 2
#define FLAG_RES  4
#define FLAG_OSPL 8
#define MG_SMEM (4 * 32768)

__global__ __launch_bounds__(512, 1) void mgemm6_kernel(
    const bf16* __restrict__ Ah, const bf16* __restrict__ Al,
    const bf16* __restrict__ Bh, const bf16* __restrict__ Bl,
    const float* __restrict__ bias, const float* __restrict__ res,
    float* __restrict__ C, bf16* __restrict__ Oh, bf16* __restrict__ Ol,
    int M, int N, int K, int flags) {
    extern __shared__ char sm[];
    uint32_t smb = smem_u32(sm);

    int tid = threadIdx.x;
    int lane = tid & 31, wid = tid >> 5;
    int warp_m = wid >> 2, warp_n = wid & 3;
    int rowBase = blockIdx.x * 128, colBase = blockIdx.y * 128;

    float acc[2][4][4];
    #pragma unroll
    for (int i = 0; i < 2; i++)
        #pragma unroll
        for (int j = 0; j < 4; j++)
            #pragma unroll
            for (int q = 0; q < 4; q++) acc[i][j][q] = 0.0f;

    uint32_t offA[2][2][2], offB[2][2][2];
    #pragma unroll
    for (int kk = 0; kk < 2; ++kk) {
        #pragma unroll
        for (int mt = 0; mt < 2; ++mt) {
            int r = warp_m * 32 + mt * 16 + (lane & 15);
            int ch = kk * 2 + (lane >> 4);
            offA[kk][mt][0] = (uint32_t)(r * 128 + ((ch ^ (r & 7)) * 16));
            offA[kk][mt][1] = (uint32_t)(r * 128 + (((ch + 4) ^ (r & 7)) * 16));
        }
        #pragma unroll
        for (int g2 = 0; g2 < 2; ++g2) {
            int n = warp_n * 32 + g2 * 16 + ((lane >> 4) << 3) + (lane & 7);
            int ch = kk * 2 + ((lane >> 3) & 1);
            offB[kk][g2][0] = (uint32_t)(16384 + n * 128 + ((ch ^ (n & 7)) * 16));
            offB[kk][g2][1] = (uint32_t)(16384 + n * 128 + (((ch + 4) ^ (n & 7)) * 16));
        }
    }

    int S = K >> 5;

    auto load_stage = [&](int s, int buf) {
        uint32_t sb = smb + buf * 32768;
        const bf16* gAh = Ah + (size_t)rowBase * K + s * 32;
        const bf16* gAl = Al + (size_t)rowBase * K + s * 32;
        const bf16* gBh = Bh + (size_t)colBase * K + s * 32;
        const bf16* gBl = Bl + (size_t)colBase * K + s * 32;
        #pragma unroll
        for (int i = 0; i < 2; i++) {
            int f = tid + i * 512;
            int r = f >> 3, c = f & 7;
            uint32_t so = (uint32_t)(r * 128 + ((c ^ (r & 7)) * 16));
            const bf16* srcA = (c < 4) ? (gAh + (size_t)r * K + c * 8)
                                       : (gAl + (size_t)r * K + (c - 4) * 8);
            const bf16* srcB = (c < 4) ? (gBh + (size_t)r * K + c * 8)
                                       : (gBl + (size_t)r * K + (c - 4) * 8);
            cpa16(sb + so, srcA);
            cpa16(sb + 16384 + so, srcB);
        }
        CPA_COMMIT();
    };

    uint32_t ah[2][2][4], al[2][2][4], bh[2][8], bl[2][8];

    auto ldfrags = [&](int fb, int kk, uint32_t sb) {
        #pragma unroll
        for (int mt = 0; mt < 2; ++mt) {
            LDSM4(ah[fb][mt], sb + offA[kk][mt][0]);
            LDSM4(al[fb][mt], sb + offA[kk][mt][1]);
        }
        #pragma unroll
        for (int g2 = 0; g2 < 2; ++g2) {
            LDSM4(&bh[fb][g2 * 4], sb + offB[kk][g2][0]);
            LDSM4(&bl[fb][g2 * 4], sb + offB[kk][g2][1]);
        }
    };

    auto do_mma = [&](int fb) {
        #pragma unroll
        for (int mt = 0; mt < 2; ++mt)
            #pragma unroll
            for (int nt = 0; nt < 4; ++nt) {
                uint32_t* ph = &bh[fb][(nt >> 1) * 4 + (nt & 1) * 2];
                uint32_t* pl = &bl[fb][(nt >> 1) * 4 + (nt & 1) * 2];
                MMA16816(acc[mt][nt], ah[fb][mt], ph);
                MMA16816(acc[mt][nt], ah[fb][mt], pl);
                MMA16816(acc[mt][nt], al[fb][mt], ph);
            }
    };

    load_stage(0, 0);
    load_stage(1, 1);
    load_stage(2, 2);
    CPA_WAIT1();
    __syncthreads();
    ldfrags(0, 0, smb);

    for (int s = 0; s < S; ++s) {
        uint32_t sb = smb + (s & 3) * 32768;

        if (s + 3 < S) load_stage(s + 3, (s + 3) & 3);
        else CPA_COMMIT();

        ldfrags(1, 1, sb);
        do_mma(0);

        CPA_WAIT1();
        if (s + 1 < S)
            ldfrags(0, 0, smb + ((s + 1) & 3) * 32768);
        do_mma(1);
        __syncthreads();
    }

    #pragma unroll
    for (int mt = 0; mt < 2; ++mt) {
        #pragma unroll
        for (int nt = 0; nt < 4; ++nt) {
            int col = colBase + warp_n * 32 + nt * 8 + (lane & 3) * 2;
            int row0 = rowBase + warp_m * 32 + mt * 16 + (lane >> 2);
            #pragma unroll
            for (int half = 0; half < 2; ++half) {
                size_t row = (size_t)(row0 + half * 8);
                float v0 = acc[mt][nt][half * 2 + 0];
                float v1 = acc[mt][nt][half * 2 + 1];
                if (flags & FLAG_BIAS) { v0 += bias[col]; v1 += bias[col + 1]; }
                if (flags & FLAG_GELU) {
                    v0 = 0.5f * v0 * (1.0f + erff(v0 * 0.70710678118654752f));
                    v1 = 0.5f * v1 * (1.0f + erff(v1 * 0.70710678118654752f));
                }
                if (flags & FLAG_RES) {
                    float2 rv = *(const float2*)(res + row * N + col);
                    v0 += rv.x; v1 += rv.y;
                }
                if (flags & FLAG_OSPL) {
                    float h0 = __bfloat162float(__float2bfloat16(v0));
                    float h1 = __bfloat162float(__float2bfloat16(v1));
                    *(uint32_t*)(Oh + row * N + col) = pack_bf2(v0, v1);
                    *(uint32_t*)(Ol + row * N + col) = pack_bf2(v0 - h0, v1 - h1);
                } else {
                    *(float2*)(C + row * N + col) = make_float2(v0, v1);
                }
            }
        }
    }
}

// ============== MMA flash attention (split-bf16, 4 warps, 64-q tile) =========
// qkv hi/lo: [NTOK][3072]. smem: Qh Ql Kh Kl Vh Vl, each 64 rows x 128B swizzled.
#define FA_SMEM 49152
#define QKVS 3072

__global__ __launch_bounds__(128) void mattn_kernel(
    const bf16* __restrict__ qkvh, const bf16* __restrict__ qkvl,
    bf16* __restrict__ oh, bf16* __restrict__ ol) {
    extern __shared__ char smc[];
    uint32_t smb = smem_u32(smc);
    uint32_t Qh = smb, Ql = smb + 8192;
    uint32_t Kh = smb + 16384, Kl = smb + 24576;
    uint32_t Vh = smb + 32768, Vl = smb + 40960;

    int qt = gridDim.x - 1 - blockIdx.x;   // long blocks first
    int bh = blockIdx.y;
    int b = bh >> 4, h = bh & 15;
    int tid = threadIdx.x, lane = tid & 31, w = tid >> 5;
    int qBase = qt * 64;
    size_t rowQ = (size_t)(b * SEQ + qBase);

    // stage Q (hi/lo)
    #pragma unroll
    for (int i = 0; i < 4; ++i) {
        int f = tid + i * 128;
        int r = f >> 3, c = f & 7;
        uint32_t so = (uint32_t)(r * 128 + ((c ^ (r & 7)) * 16));
        size_t g = (rowQ + r) * QKVS + h * HD + c * 8;
        cpa16(Qh + so, qkvh + g);
        cpa16(Ql + so, qkvl + g);
    }
    CPA_COMMIT();

    float m0 = -1e30f, m1 = -1e30f, l0 = 0.0f, l1 = 0.0f;
    float oacc[8][4];
    #pragma unroll
    for (int nt = 0; nt < 8; ++nt)
        #pragma unroll
        for (int e = 0; e < 4; ++e) oacc[nt][e] = 0.0f;

    int r0g = qBase + w * 16 + (lane >> 2);    // global q row (half 0)

    for (int kt = 0; kt <= qt; ++kt) {
        int kBase = kt * 64;
        size_t rowK = (size_t)(b * SEQ + kBase);
        __syncthreads();                        // prior K/V reads done
        #pragma unroll
        for (int i = 0; i < 4; ++i) {
            int f = tid + i * 128;
            int r = f >> 3, c = f & 7;
            uint32_t so = (uint32_t)(r * 128 + ((c ^ (r & 7)) * 16));
            size_t gk = (rowK + r) * QKVS + 1024 + h * HD + c * 8;
            cpa16(Kh + so, qkvh + gk);
            cpa16(Kl + so, qkvl + gk);
            cpa16(Vh + so, qkvh + gk + 1024);
            cpa16(Vl + so, qkvl + gk + 1024);
        }
        CPA_COMMIT();
        CPA_WAIT0();
        __syncthreads();

        // ---- QK^T: sacc[8 ntiles][4] ----
        float sacc[8][4];
        #pragma unroll
        for (int nt = 0; nt < 8; ++nt)
            #pragma unroll
            for (int e = 0; e < 4; ++e) sacc[nt][e] = 0.0f;

        #pragma unroll
        for (int kk = 0; kk < 4; ++kk) {        // d slices of 16
            uint32_t aq[4], aql[4];
            {
                int r = w * 16 + (lane & 15);
                int ch = kk * 2 + (lane >> 4);
                uint32_t so = (uint32_t)(r * 128 + ((ch ^ (r & 7)) * 16));
                LDSM4(aq, Qh + so);
                LDSM4(aql, Ql + so);
            }
            #pragma unroll
            for (int g2 = 0; g2 < 4; ++g2) {    // s groups of 16
                int n = g2 * 16 + ((lane >> 4) << 3) + (lane & 7);
                int ch = kk * 2 + ((lane >> 3) & 1);
                uint32_t so = (uint32_t)(n * 128 + ((ch ^ (n & 7)) * 16));
                uint32_t bk[4], bkl[4];
                LDSM4(bk, Kh + so);
                LDSM4(bkl, Kl + so);
                MMA16816(sacc[g2*2],     aq,  &bk[0]);
                MMA16816(sacc[g2*2],     aq,  &bkl[0]);
                MMA16816(sacc[g2*2],     aql, &bk[0]);
                MMA16816(sacc[g2*2 + 1], aq,  &bk[2]);
                MMA16816(sacc[g2*2 + 1], aq,  &bkl[2]);
                MMA16816(sacc[g2*2 + 1], aql, &bk[2]);
            }
        }

        // ---- softmax (rows lane>>2 and +8) ----
        bool diag = (kt == qt);
        float mx0 = -1e30f, mx1 = -1e30f;
        #pragma unroll
        for (int nt = 0; nt < 8; ++nt) {
            int c0 = kBase + nt * 8 + (lane & 3) * 2;
            #pragma unroll
            for (int e = 0; e < 2; ++e) {
                float v0 = sacc[nt][e] * 0.125f;
                float v1 = sacc[nt][2 + e] * 0.125f;
                if (diag) {
                    if (c0 + e > r0g)     v0 = -1e30f;
                    if (c0 + e > r0g + 8) v1 = -1e30f;
                }
                sacc[nt][e] = v0; sacc[nt][2 + e] = v1;
                mx0 = fmaxf(mx0, v0); mx1 = fmaxf(mx1, v1);
            }
        }
        mx0 = fmaxf(mx0, __shfl_xor_sync(0xffffffffu, mx0, 1));
        mx0 = fmaxf(mx0, __shfl_xor_sync(0xffffffffu, mx0, 2));
        mx1 = fmaxf(mx1, __shfl_xor_sync(0xffffffffu, mx1, 1));
        mx1 = fmaxf(mx1, __shfl_xor_sync(0xffffffffu, mx1, 2));
        float mn0 = fmaxf(m0, mx0), mn1 = fmaxf(m1, mx1);
        float cr0 = __expf(m0 - mn0), cr1 = __expf(m1 - mn1);
        float ps0 = 0.0f, ps1 = 0.0f;
        uint32_t pah[4][4], pal[4][4];
        #pragma unroll
        for (int nt = 0; nt < 8; ++nt) {
            float p0 = __expf(sacc[nt][0] - mn0);
            float p1 = __expf(sacc[nt][1] - mn0);
            float p2 = __expf(sacc[nt][2] - mn1);
            float p3 = __expf(sacc[nt][3] - mn1);
            ps0 += p0 + p1; ps1 += p2 + p3;
            float h0 = __bfloat162float(__float2bfloat16(p0));
            float h1 = __bfloat162float(__float2bfloat16(p1));
            float h2 = __bfloat162float(__float2bfloat16(p2));
            float h3 = __bfloat162float(__float2bfloat16(p3));
            int t = nt >> 1, base = (nt & 1) * 2;
            pah[t][base + 0] = pack_bf2(p0, p1);
            pah[t][base + 1] = pack_bf2(p2, p3);
            pal[t][base + 0] = pack_bf2(p0 - h0, p1 - h1);
            pal[t][base + 1] = pack_bf2(p2 - h2, p3 - h3);
        }
        ps0 += __shfl_xor_sync(0xffffffffu, ps0, 1);
        ps0 += __shfl_xor_sync(0xffffffffu, ps0, 2);
        ps1 += __shfl_xor_sync(0xffffffffu, ps1, 1);
        ps1 += __shfl_xor_sync(0xffffffffu, ps1, 2);
        l0 = l0 * cr0 + ps0; m0 = mn0;
        l1 = l1 * cr1 + ps1; m1 = mn1;
        #pragma unroll
        for (int nt = 0; nt < 8; ++nt) {
            oacc[nt][0] *= cr0; oacc[nt][1] *= cr0;
            oacc[nt][2] *= cr1; oacc[nt][3] *= cr1;
        }

        // ---- PV: o[16q][64d] += P[16q][64s] V[64s][64d] (V^T via trans ldsm) --
        #pragma unroll
        for (int t = 0; t < 4; ++t) {           // s slices of 16
            #pragma unroll
            for (int g = 0; g < 4; ++g) {       // d pairs of 16
                int r = t * 16 + ((lane >> 3) & 1) * 8 + (lane & 7);
                int ch = g * 2 + (lane >> 4);
                uint32_t so = (uint32_t)(r * 128 + ((ch ^ (r & 7)) * 16));
                uint32_t vh[4], vl[4];
                LDSM4T(vh, Vh + so);
                LDSM4T(vl, Vl + so);
                MMA16816(oacc[g*2],     pah[t], &vh[0]);
                MMA16816(oacc[g*2],     pah[t], &vl[0]);
                MMA16816(oacc[g*2],     pal[t], &vh[0]);
                MMA16816(oacc[g*2 + 1], pah[t], &vh[2]);
                MMA16816(oacc[g*2 + 1], pah[t], &vl[2]);
                MMA16816(oacc[g*2 + 1], pal[t], &vh[2]);
            }
        }
    }

    // ---- epilogue: hi/lo bf16 out, stride EMB ----
    float i0 = 1.0f / l0, i1 = 1.0f / l1;
    size_t row0 = (size_t)(b * SEQ) + qBase + w * 16 + (lane >> 2);
    #pragma unroll
    for (int nt = 0; nt < 8; ++nt) {
        int col = h * HD + nt * 8 + (lane & 3) * 2;
        float v0 = oacc[nt][0] * i0, v1 = oacc[nt][1] * i0;
        float v2 = oacc[nt][2] * i1, v3 = oacc[nt][3] * i1;
        float h0 = __bfloat162float(__float2bfloat16(v0));
        float h1 = __bfloat162float(__float2bfloat16(v1));
        float h2 = __bfloat162float(__float2bfloat16(v2));
        float h3 = __bfloat162float(__float2bfloat16(v3));
        *(uint32_t*)(oh + row0 * EMB + col)       = pack_bf2(v0, v1);
        *(uint32_t*)(ol + row0 * EMB + col)       = pack_bf2(v0 - h0, v1 - h1);
        *(uint32_t*)(oh + (row0 + 8) * EMB + col) = pack_bf2(v2, v3);
        *(uint32_t*)(ol + (row0 + 8) * EMB + col) = pack_bf2(v2 - h2, v3 - h3);
    }
}

// ---------------- launch ----------------------------------------------------
extern "C" void kernel_launch(void* const* d_in, const int* in_sizes, int n_in,
                              void* d_out, int out_size) {
    const int*   idx    = (const int*)d_in[0];
    const float* tok    = (const float*)d_in[1];
    const float* pos    = (const float*)d_in[2];
    const float* Wq     = (const float*)d_in[3];
    const float* Wk     = (const float*)d_in[4];
    const float* Wv     = (const float*)d_in[5];
    const float* Wp     = (const float*)d_in[6];
    const float* bp     = (const float*)d_in[7];
    const float* ln1_g  = (const float*)d_in[8];
    const float* ln1_b  = (const float*)d_in[9];
    const float* ln2_g  = (const float*)d_in[10];
    const float* ln2_b  = (const float*)d_in[11];
    const float* W1     = (const float*)d_in[12];
    const float* b1     = (const float*)d_in[13];
    const float* W2     = (const float*)d_in[14];
    const float* b2     = (const float*)d_in[15];
    const float* lnf_g  = (const float*)d_in[16];
    const float* lnf_b  = (const float*)d_in[17];
    const float* Wout   = (const float*)d_in[18];

    float *x;
    bf16 *hh, *hl, *qkvh, *qkvl, *ohh, *ohl, *uh, *ul;
    bf16 *wqkvh, *wqkvl, *wph, *wpl, *w1h, *w1l, *w2h, *w2l, *woh, *wol;
    cudaGetSymbolAddress((void**)&x, g_x);
    cudaGetSymbolAddress((void**)&hh, g_h_h);
    cudaGetSymbolAddress((void**)&hl, g_h_l);
    cudaGetSymbolAddress((void**)&qkvh, g_qkv_h);
    cudaGetSymbolAddress((void**)&qkvl, g_qkv_l);
    cudaGetSymbolAddress((void**)&ohh, g_o_h);
    cudaGetSymbolAddress((void**)&ohl, g_o_l);
    cudaGetSymbolAddress((void**)&uh, g_u_h);
    cudaGetSymbolAddress((void**)&ul, g_u_l);
    cudaGetSymbolAddress((void**)&wqkvh, g_Wqkv_h); cudaGetSymbolAddress((void**)&wqkvl, g_Wqkv_l);
    cudaGetSymbolAddress((void**)&wph, g_Wp_h);     cudaGetSymbolAddress((void**)&wpl, g_Wp_l);
    cudaGetSymbolAddress((void**)&w1h, g_W1_h);     cudaGetSymbolAddress((void**)&w1l, g_W1_l);
    cudaGetSymbolAddress((void**)&w2h, g_W2_h);     cudaGetSymbolAddress((void**)&w2l, g_W2_l);
    cudaGetSymbolAddress((void**)&woh, g_Wo_h);     cudaGetSymbolAddress((void**)&wol, g_Wo_l);

    cudaFuncSetAttribute(mgemm6_kernel, cudaFuncAttributeMaxDynamicSharedMemorySize, MG_SMEM);
    cudaFuncSetAttribute(mattn_kernel, cudaFuncAttributeMaxDynamicSharedMemorySize, FA_SMEM);

    tconv_all<<<130304, dim3(32, 8)>>>(Wq, Wk, Wv, Wp, W1, W2, Wout,
                                       wqkvh, wqkvl, wph, wpl, w1h, w1l,
                                       w2h, w2l, woh, wol);
    embed_kernel<<<NTOK, 256>>>(idx, tok, pos, x);

    dim3 gQKV(NTOK / 128, 3 * EMB / 128);
    dim3 gE(NTOK / 128, EMB / 128);
    dim3 gH(NTOK / 128, HID / 128);
    dim3 gV(NTOK / 128, VOCAB / 128);
    dim3 gA(SEQ / 64, 2 * NH);

    for (int l = 0; l < NL; l++) {
        size_t wo = (size_t)l * EMB * EMB;
        size_t wqo = (size_t)l * 3 * EMB * EMB;
        size_t w1o = (size_t)l * EMB * HID;

        ln_kernel<<<NTOK, 256>>>(x, ln1_g + l * EMB, ln1_b + l * EMB, hh, hl);
        mgemm6_kernel<<<gQKV, 512, MG_SMEM>>>(hh, hl, wqkvh + wqo, wqkvl + wqo,
                                              nullptr, nullptr, nullptr, qkvh, qkvl,
                                              NTOK, 3 * EMB, EMB, FLAG_OSPL);
        mattn_kernel<<<gA, 128, FA_SMEM>>>(qkvh, qkvl, ohh, ohl);
        mgemm6_kernel<<<gE, 512, MG_SMEM>>>(ohh, ohl, wph + wo, wpl + wo, bp + l * EMB, x,
                                            x, nullptr, nullptr, NTOK, EMB, EMB,
                                            FLAG_BIAS | FLAG_RES);
        ln_kernel<<<NTOK, 256>>>(x, ln2_g + l * EMB, ln2_b + l * EMB, hh, hl);
        mgemm6_kernel<<<gH, 512, MG_SMEM>>>(hh, hl, w1h + w1o, w1l + w1o, b1 + l * HID,
                                            nullptr, nullptr, uh, ul, NTOK, HID, EMB,
                                            FLAG_BIAS | FLAG_GELU | FLAG_OSPL);
        mgemm6_kernel<<<gE, 512, MG_SMEM>>>(uh, ul, w2h + w1o, w2l + w1o, b2 + l * EMB, x,
                                            x, nullptr, nullptr, NTOK, EMB, HID,
                                            FLAG_BIAS | FLAG_RES);
    }

    ln_kernel<<<NTOK, 256>>>(x, lnf_g, lnf_b, hh, hl);
    mgemm6_kernel<<<gV, 512, MG_SMEM>>>(hh, hl, woh, wol, nullptr, nullptr,
                                        (float*)d_out, nullptr, nullptr,
                                        NTOK, VOCAB, EMB, 0);
}

// round 13
// speedup vs baseline: 1.4233x; 1.0012x over previous
#include <cuda_runtime.h>
#include <cuda_bf16.h>
#include <math.h>
#include <stdint.h>

#define NTOK 4096
#define EMB  1024
#define HID  4096
#define VOCAB 32000
#define SEQ  2048
#define NH   16
#define HD   64
#define NL   8

typedef __nv_bfloat16 bf16;
typedef __nv_bfloat162 bf162;

// ---------------- device scratch --------------------------------------------
__device__ __align__(16) float g_x[NTOK * EMB];

__device__ __align__(16) bf16 g_h_h[NTOK * EMB];
__device__ __align__(16) bf16 g_h_l[NTOK * EMB];
__device__ __align__(16) bf16 g_qkv_h[NTOK * 3 * EMB];
__device__ __align__(16) bf16 g_qkv_l[NTOK * 3 * EMB];
__device__ __align__(16) bf16 g_o_h[NTOK * EMB];
__device__ __align__(16) bf16 g_o_l[NTOK * EMB];
__device__ __align__(16) bf16 g_u_h[NTOK * HID];
__device__ __align__(16) bf16 g_u_l[NTOK * HID];

// transposed weights [N][K] hi/lo; QKV fused to [3E][E] per layer
__device__ __align__(16) bf16 g_Wqkv_h[NL * 3 * EMB * EMB];
__device__ __align__(16) bf16 g_Wqkv_l[NL * 3 * EMB * EMB];
__device__ __align__(16) bf16 g_Wp_h[NL * EMB * EMB];
__device__ __align__(16) bf16 g_Wp_l[NL * EMB * EMB];
__device__ __align__(16) bf16 g_W1_h[NL * EMB * HID];
__device__ __align__(16) bf16 g_W1_l[NL * EMB * HID];
__device__ __align__(16) bf16 g_W2_h[NL * EMB * HID];
__device__ __align__(16) bf16 g_W2_l[NL * EMB * HID];
__device__ __align__(16) bf16 g_Wo_h[(size_t)VOCAB * EMB];
__device__ __align__(16) bf16 g_Wo_l[(size_t)VOCAB * EMB];

// ---------------- helpers ---------------------------------------------------
__device__ __forceinline__ uint32_t smem_u32(const void* p) {
    return (uint32_t)__cvta_generic_to_shared((void*)p);
}
__device__ __forceinline__ uint32_t pack_bf2(float a, float b) {
    bf162 t = __floats2bfloat162_rn(a, b);
    return *reinterpret_cast<uint32_t*>(&t);
}
__device__ __forceinline__ void cpa16(uint32_t dst, const void* src) {
    asm volatile("cp.async.ca.shared.global [%0], [%1], 16;" :: "r"(dst), "l"(src));
}
#define CPA_COMMIT() asm volatile("cp.async.commit_group;" ::: "memory")
#define CPA_WAIT1()  asm volatile("cp.async.wait_group 1;" ::: "memory")
#define CPA_WAIT0()  asm volatile("cp.async.wait_group 0;" ::: "memory")

#define LDSM4(r, a) \
    asm volatile("ldmatrix.sync.aligned.m8n8.x4.shared.b16 {%0,%1,%2,%3}, [%4];" \
        : "=r"((r)[0]), "=r"((r)[1]), "=r"((r)[2]), "=r"((r)[3]) : "r"(a))

#define LDSM4T(r, a) \
    asm volatile("ldmatrix.sync.aligned.m8n8.x4.trans.shared.b16 {%0,%1,%2,%3}, [%4];" \
        : "=r"((r)[0]), "=r"((r)[1]), "=r"((r)[2]), "=r"((r)[3]) : "r"(a))

#define MMA16816(d, a, b) \
    asm volatile("mma.sync.aligned.m16n8k16.row.col.f32.bf16.bf16.f32 " \
        "{%0,%1,%2,%3},{%4,%5,%6,%7},{%8,%9},{%0,%1,%2,%3};" \
        : "+f"((d)[0]), "+f"((d)[1]), "+f"((d)[2]), "+f"((d)[3]) \
        : "r"((a)[0]), "r"((a)[1]), "r"((a)[2]), "r"((a)[3]), \
          "r"((b)[0]), "r"((b)[1]))

// ---------------- all-weights transpose + split-convert ----------------------
__global__ void tconv_all(const float* __restrict__ Wq, const float* __restrict__ Wk,
                          const float* __restrict__ Wv, const float* __restrict__ Wp,
                          const float* __restrict__ W1, const float* __restrict__ W2,
                          const float* __restrict__ Wout,
                          bf16* __restrict__ qkvh, bf16* __restrict__ qkvl,
                          bf16* __restrict__ wph, bf16* __restrict__ wpl,
                          bf16* __restrict__ w1h, bf16* __restrict__ w1l,
                          bf16* __restrict__ w2h, bf16* __restrict__ w2l,
                          bf16* __restrict__ woh, bf16* __restrict__ wol) {
    __shared__ float t[32][33];
    int b = blockIdx.x;
    const float* src; bf16 *oh, *ol;
    int K, N, tilesX, tloc, rowOff = 0;

    if (b < 24576) {
        int type = b / 8192, lb = b % 8192;
        int layer = lb / 1024; tloc = lb % 1024;
        K = 1024; N = 1024; tilesX = 32;
        src = (type == 0 ? Wq : type == 1 ? Wk : Wv) + (size_t)layer * EMB * EMB;
        oh = qkvh + (size_t)layer * 3 * EMB * EMB;
        ol = qkvl + (size_t)layer * 3 * EMB * EMB;
        rowOff = type * 1024;
    } else if (b < 32768) {
        int lb = b - 24576;
        int layer = lb / 1024; tloc = lb % 1024;
        K = 1024; N = 1024; tilesX = 32;
        src = Wp + (size_t)layer * EMB * EMB;
        oh = wph + (size_t)layer * EMB * EMB;
        ol = wpl + (size_t)layer * EMB * EMB;
    } else if (b < 65536) {
        int lb = b - 32768;
        int layer = lb / 4096; tloc = lb % 4096;
        K = 1024; N = 4096; tilesX = 128;
        src = W1 + (size_t)layer * EMB * HID;
        oh = w1h + (size_t)layer * EMB * HID;
        ol = w1l + (size_t)layer * EMB * HID;
    } else if (b < 98304) {
        int lb = b - 65536;
        int layer = lb / 4096; tloc = lb % 4096;
        K = 4096; N = 1024; tilesX = 32;
        src = W2 + (size_t)layer * HID * EMB;
        oh = w2h + (size_t)layer * HID * EMB;
        ol = w2l + (size_t)layer * HID * EMB;
    } else {
        tloc = b - 98304;
        K = 1024; N = VOCAB; tilesX = 1000;
        src = Wout; oh = woh; ol = wol;
    }

    int bx = (tloc % tilesX) * 32;
    int by = (tloc / tilesX) * 32;
    int x = threadIdx.x, y = threadIdx.y;
    #pragma unroll
    for (int i = 0; i < 4; i++)
        t[y + i * 8][x] = src[(size_t)(by + y + i * 8) * N + bx + x];
    __syncthreads();
    #pragma unroll
    for (int i = 0; i < 4; i++) {
        int n = bx + y + i * 8, k = by + x;
        float v = t[x][y + i * 8];
        bf16 hv = __float2bfloat16(v);
        oh[(size_t)(rowOff + n) * K + k] = hv;
        ol[(size_t)(rowOff + n) * K + k] = __float2bfloat16(v - __bfloat162float(hv));
    }
}

// ---------------- embed ------------------------------------------------------
__global__ void embed_kernel(const int* __restrict__ idx, const float* __restrict__ tok,
                             const float* __restrict__ pos, float* __restrict__ x) {
    int n = blockIdx.x, e4 = threadIdx.x, t = n & (SEQ - 1);
    float4 a = ((const float4*)(tok + (size_t)idx[n] * EMB))[e4];
    float4 b = ((const float4*)(pos + (size_t)t * EMB))[e4];
    a.x += b.x; a.y += b.y; a.z += b.z; a.w += b.w;
    ((float4*)(x + (size_t)n * EMB))[e4] = a;
}

// ---------------- layernorm -> hi/lo bf16 ------------------------------------
__device__ __forceinline__ float block_sum_256(float s, float* red) {
    #pragma unroll
    for (int o = 16; o; o >>= 1) s += __shfl_xor_sync(0xffffffffu, s, o);
    if ((threadIdx.x & 31) == 0) red[threadIdx.x >> 5] = s;
    __syncthreads();
    if (threadIdx.x < 32) {
        float t = (threadIdx.x < 8) ? red[threadIdx.x] : 0.0f;
        #pragma unroll
        for (int o = 4; o; o >>= 1) t += __shfl_xor_sync(0xffffffffu, t, o);
        if (threadIdx.x == 0) red[0] = t;
    }
    __syncthreads();
    float r = red[0];
    __syncthreads();
    return r;
}

__global__ void ln_kernel(const float* __restrict__ x, const float* __restrict__ g,
                          const float* __restrict__ b, bf16* __restrict__ oh,
                          bf16* __restrict__ ol) {
    __shared__ float red[8];
    int n = blockIdx.x, tid = threadIdx.x;
    float4 v = ((const float4*)(x + (size_t)n * EMB))[tid];
    float mu = block_sum_256(v.x + v.y + v.z + v.w, red) * (1.0f / EMB);
    float dx = v.x - mu, dy = v.y - mu, dz = v.z - mu, dw = v.w - mu;
    float var = block_sum_256(dx*dx + dy*dy + dz*dz + dw*dw, red) * (1.0f / EMB);
    float rs = rsqrtf(var + 1e-5f);
    float4 gg = ((const float4*)g)[tid];
    float4 bb = ((const float4*)b)[tid];
    float r0 = dx*rs*gg.x + bb.x, r1 = dy*rs*gg.y + bb.y;
    float r2 = dz*rs*gg.z + bb.z, r3 = dw*rs*gg.w + bb.w;
    float h0 = __bfloat162float(__float2bfloat16(r0));
    float h1 = __bfloat162float(__float2bfloat16(r1));
    float h2 = __bfloat162float(__float2bfloat16(r2));
    float h3 = __bfloat162float(__float2bfloat16(r3));
    size_t o = (size_t)n * EMB + tid * 4;
    *(uint2*)(oh + o) = make_uint2(pack_bf2(r0, r1), pack_bf2(r2, r3));
    *(uint2*)(ol + o) = make_uint2(pack_bf2(r0 - h0, r1 - h1), pack_bf2(r2 - h2, r3 - h3));
}

// ============= 16-warp cross-stage-pipelined split-bf16 MMA GEMM =============
// (exact mgemm6 from R9 — best measured GEMM)
#define FLAG_BIAS 1
#define FLAG_GELU 2
#define FLAG_RES  4
#define FLAG_OSPL 8
#define MG_SMEM (4 * 32768)

__global__ __launch_bounds__(512, 1) void mgemm6_kernel(
    const bf16* __restrict__ Ah, const bf16* __restrict__ Al,
    const bf16* __restrict__ Bh, const bf16* __restrict__ Bl,
    const float* __restrict__ bias, const float* __restrict__ res,
    float* __restrict__ C, bf16* __restrict__ Oh, bf16* __restrict__ Ol,
    int M, int N, int K, int flags) {
    extern __shared__ char sm[];
    uint32_t smb = smem_u32(sm);

    int tid = threadIdx.x;
    int lane = tid & 31, wid = tid >> 5;
    int warp_m = wid >> 2, warp_n = wid & 3;
    int rowBase = blockIdx.x * 128, colBase = blockIdx.y * 128;

    float acc[2][4][4];
    #pragma unroll
    for (int i = 0; i < 2; i++)
        #pragma unroll
        for (int j = 0; j < 4; j++)
            #pragma unroll
            for (int q = 0; q < 4; q++) acc[i][j][q] = 0.0f;

    uint32_t offA[2][2][2], offB[2][2][2];
    #pragma unroll
    for (int kk = 0; kk < 2; ++kk) {
        #pragma unroll
        for (int mt = 0; mt < 2; ++mt) {
            int r = warp_m * 32 + mt * 16 + (lane & 15);
            int ch = kk * 2 + (lane >> 4);
            offA[kk][mt][0] = (uint32_t)(r * 128 + ((ch ^ (r & 7)) * 16));
            offA[kk][mt][1] = (uint32_t)(r * 128 + (((ch + 4) ^ (r & 7)) * 16));
        }
        #pragma unroll
        for (int g2 = 0; g2 < 2; ++g2) {
            int n = warp_n * 32 + g2 * 16 + ((lane >> 4) << 3) + (lane & 7);
            int ch = kk * 2 + ((lane >> 3) & 1);
            offB[kk][g2][0] = (uint32_t)(16384 + n * 128 + ((ch ^ (n & 7)) * 16));
            offB[kk][g2][1] = (uint32_t)(16384 + n * 128 + (((ch + 4) ^ (n & 7)) * 16));
        }
    }

    int S = K >> 5;

    auto load_stage = [&](int s, int buf) {
        uint32_t sb = smb + buf * 32768;
        const bf16* gAh = Ah + (size_t)rowBase * K + s * 32;
        const bf16* gAl = Al + (size_t)rowBase * K + s * 32;
        const bf16* gBh = Bh + (size_t)colBase * K + s * 32;
        const bf16* gBl = Bl + (size_t)colBase * K + s * 32;
        #pragma unroll
        for (int i = 0; i < 2; i++) {
            int f = tid + i * 512;
            int r = f >> 3, c = f & 7;
            uint32_t so = (uint32_t)(r * 128 + ((c ^ (r & 7)) * 16));
            const bf16* srcA = (c < 4) ? (gAh + (size_t)r * K + c * 8)
                                       : (gAl + (size_t)r * K + (c - 4) * 8);
            const bf16* srcB = (c < 4) ? (gBh + (size_t)r * K + c * 8)
                                       : (gBl + (size_t)r * K + (c - 4) * 8);
            cpa16(sb + so, srcA);
            cpa16(sb + 16384 + so, srcB);
        }
        CPA_COMMIT();
    };

    uint32_t ah[2][2][4], al[2][2][4], bh[2][8], bl[2][8];

    auto ldfrags = [&](int fb, int kk, uint32_t sb) {
        #pragma unroll
        for (int mt = 0; mt < 2; ++mt) {
            LDSM4(ah[fb][mt], sb + offA[kk][mt][0]);
            LDSM4(al[fb][mt], sb + offA[kk][mt][1]);
        }
        #pragma unroll
        for (int g2 = 0; g2 < 2; ++g2) {
            LDSM4(&bh[fb][g2 * 4], sb + offB[kk][g2][0]);
            LDSM4(&bl[fb][g2 * 4], sb + offB[kk][g2][1]);
        }
    };

    auto do_mma = [&](int fb) {
        #pragma unroll
        for (int mt = 0; mt < 2; ++mt)
            #pragma unroll
            for (int nt = 0; nt < 4; ++nt) {
                uint32_t* ph = &bh[fb][(nt >> 1) * 4 + (nt & 1) * 2];
                uint32_t* pl = &bl[fb][(nt >> 1) * 4 + (nt & 1) * 2];
                MMA16816(acc[mt][nt], ah[fb][mt], ph);
                MMA16816(acc[mt][nt], ah[fb][mt], pl);
                MMA16816(acc[mt][nt], al[fb][mt], ph);
            }
    };

    load_stage(0, 0);
    load_stage(1, 1);
    load_stage(2, 2);
    CPA_WAIT1();
    __syncthreads();
    ldfrags(0, 0, smb);

    for (int s = 0; s < S; ++s) {
        uint32_t sb = smb + (s & 3) * 32768;

        if (s + 3 < S) load_stage(s + 3, (s + 3) & 3);
        else CPA_COMMIT();

        ldfrags(1, 1, sb);
        do_mma(0);

        CPA_WAIT1();
        if (s + 1 < S)
            ldfrags(0, 0, smb + ((s + 1) & 3) * 32768);
        do_mma(1);
        __syncthreads();
    }

    #pragma unroll
    for (int mt = 0; mt < 2; ++mt) {
        #pragma unroll
        for (int nt = 0; nt < 4; ++nt) {
            int col = colBase + warp_n * 32 + nt * 8 + (lane & 3) * 2;
            int row0 = rowBase + warp_m * 32 + mt * 16 + (lane >> 2);
            #pragma unroll
            for (int half = 0; half < 2; ++half) {
                size_t row = (size_t)(row0 + half * 8);
                float v0 = acc[mt][nt][half * 2 + 0];
                float v1 = acc[mt][nt][half * 2 + 1];
                if (flags & FLAG_BIAS) { v0 += bias[col]; v1 += bias[col + 1]; }
                if (flags & FLAG_GELU) {
                    v0 = 0.5f * v0 * (1.0f + erff(v0 * 0.70710678118654752f));
                    v1 = 0.5f * v1 * (1.0f + erff(v1 * 0.70710678118654752f));
                }
                if (flags & FLAG_RES) {
                    float2 rv = *(const float2*)(res + row * N + col);
                    v0 += rv.x; v1 += rv.y;
                }
                if (flags & FLAG_OSPL) {
                    float h0 = __bfloat162float(__float2bfloat16(v0));
                    float h1 = __bfloat162float(__float2bfloat16(v1));
                    *(uint32_t*)(Oh + row * N + col) = pack_bf2(v0, v1);
                    *(uint32_t*)(Ol + row * N + col) = pack_bf2(v0 - h0, v1 - h1);
                } else {
                    *(float2*)(C + row * N + col) = make_float2(v0, v1);
                }
            }
        }
    }
}

// ============== MMA flash attention (split-bf16, 4 warps, 64-q tile) =========
// qkv hi/lo: [NTOK][3072]. smem: Qh Ql Kh Kl Vh Vl, each 64 rows x 128B swizzled.
#define FA_SMEM 49152
#define QKVS 3072

__global__ __launch_bounds__(128) void mattn_kernel(
    const bf16* __restrict__ qkvh, const bf16* __restrict__ qkvl,
    bf16* __restrict__ oh, bf16* __restrict__ ol) {
    extern __shared__ char smc[];
    uint32_t smb = smem_u32(smc);
    uint32_t Qh = smb, Ql = smb + 8192;
    uint32_t Kh = smb + 16384, Kl = smb + 24576;
    uint32_t Vh = smb + 32768, Vl = smb + 40960;

    int qt = gridDim.x - 1 - blockIdx.x;   // long blocks first
    int bh = blockIdx.y;
    int b = bh >> 4, h = bh & 15;
    int tid = threadIdx.x, lane = tid & 31, w = tid >> 5;
    int qBase = qt * 64;
    size_t rowQ = (size_t)(b * SEQ + qBase);

    // stage Q (hi/lo)
    #pragma unroll
    for (int i = 0; i < 4; ++i) {
        int f = tid + i * 128;
        int r = f >> 3, c = f & 7;
        uint32_t so = (uint32_t)(r * 128 + ((c ^ (r & 7)) * 16));
        size_t g = (rowQ + r) * QKVS + h * HD + c * 8;
        cpa16(Qh + so, qkvh + g);
        cpa16(Ql + so, qkvl + g);
    }
    CPA_COMMIT();

    float m0 = -1e30f, m1 = -1e30f, l0 = 0.0f, l1 = 0.0f;
    float oacc[8][4];
    #pragma unroll
    for (int nt = 0; nt < 8; ++nt)
        #pragma unroll
        for (int e = 0; e < 4; ++e) oacc[nt][e] = 0.0f;

    int r0g = qBase + w * 16 + (lane >> 2);    // global q row (half 0)

    for (int kt = 0; kt <= qt; ++kt) {
        int kBase = kt * 64;
        size_t rowK = (size_t)(b * SEQ + kBase);
        __syncthreads();                        // prior K/V reads done
        #pragma unroll
        for (int i = 0; i < 4; ++i) {
            int f = tid + i * 128;
            int r = f >> 3, c = f & 7;
            uint32_t so = (uint32_t)(r * 128 + ((c ^ (r & 7)) * 16));
            size_t gk = (rowK + r) * QKVS + 1024 + h * HD + c * 8;
            cpa16(Kh + so, qkvh + gk);
            cpa16(Kl + so, qkvl + gk);
            cpa16(Vh + so, qkvh + gk + 1024);
            cpa16(Vl + so, qkvl + gk + 1024);
        }
        CPA_COMMIT();
        CPA_WAIT0();
        __syncthreads();

        // ---- QK^T: sacc[8 ntiles][4] ----
        float sacc[8][4];
        #pragma unroll
        for (int nt = 0; nt < 8; ++nt)
            #pragma unroll
            for (int e = 0; e < 4; ++e) sacc[nt][e] = 0.0f;

        #pragma unroll
        for (int kk = 0; kk < 4; ++kk) {        // d slices of 16
            uint32_t aq[4], aql[4];
            {
                int r = w * 16 + (lane & 15);
                int ch = kk * 2 + (lane >> 4);
                uint32_t so = (uint32_t)(r * 128 + ((ch ^ (r & 7)) * 16));
                LDSM4(aq, Qh + so);
                LDSM4(aql, Ql + so);
            }
            #pragma unroll
            for (int g2 = 0; g2 < 4; ++g2) {    // s groups of 16
                int n = g2 * 16 + ((lane >> 4) << 3) + (lane & 7);
                int ch = kk * 2 + ((lane >> 3) & 1);
                uint32_t so = (uint32_t)(n * 128 + ((ch ^ (n & 7)) * 16));
                uint32_t bk[4], bkl[4];
                LDSM4(bk, Kh + so);
                LDSM4(bkl, Kl + so);
                MMA16816(sacc[g2*2],     aq,  &bk[0]);
                MMA16816(sacc[g2*2],     aq,  &bkl[0]);
                MMA16816(sacc[g2*2],     aql, &bk[0]);
                MMA16816(sacc[g2*2 + 1], aq,  &bk[2]);
                MMA16816(sacc[g2*2 + 1], aq,  &bkl[2]);
                MMA16816(sacc[g2*2 + 1], aql, &bk[2]);
            }
        }

        // ---- softmax (rows lane>>2 and +8) ----
        bool diag = (kt == qt);
        float mx0 = -1e30f, mx1 = -1e30f;
        #pragma unroll
        for (int nt = 0; nt < 8; ++nt) {
            int c0 = kBase + nt * 8 + (lane & 3) * 2;
            #pragma unroll
            for (int e = 0; e < 2; ++e) {
                float v0 = sacc[nt][e] * 0.125f;
                float v1 = sacc[nt][2 + e] * 0.125f;
                if (diag) {
                    if (c0 + e > r0g)     v0 = -1e30f;
                    if (c0 + e > r0g + 8) v1 = -1e30f;
                }
                sacc[nt][e] = v0; sacc[nt][2 + e] = v1;
                mx0 = fmaxf(mx0, v0); mx1 = fmaxf(mx1, v1);
            }
        }
        mx0 = fmaxf(mx0, __shfl_xor_sync(0xffffffffu, mx0, 1));
        mx0 = fmaxf(mx0, __shfl_xor_sync(0xffffffffu, mx0, 2));
        mx1 = fmaxf(mx1, __shfl_xor_sync(0xffffffffu, mx1, 1));
        mx1 = fmaxf(mx1, __shfl_xor_sync(0xffffffffu, mx1, 2));
        float mn0 = fmaxf(m0, mx0), mn1 = fmaxf(m1, mx1);
        float cr0 = __expf(m0 - mn0), cr1 = __expf(m1 - mn1);
        float ps0 = 0.0f, ps1 = 0.0f;
        uint32_t pah[4][4], pal[4][4];
        #pragma unroll
        for (int nt = 0; nt < 8; ++nt) {
            float p0 = __expf(sacc[nt][0] - mn0);
            float p1 = __expf(sacc[nt][1] - mn0);
            float p2 = __expf(sacc[nt][2] - mn1);
            float p3 = __expf(sacc[nt][3] - mn1);
            ps0 += p0 + p1; ps1 += p2 + p3;
            float h0 = __bfloat162float(__float2bfloat16(p0));
            float h1 = __bfloat162float(__float2bfloat16(p1));
            float h2 = __bfloat162float(__float2bfloat16(p2));
            float h3 = __bfloat162float(__float2bfloat16(p3));
            int t = nt >> 1, base = (nt & 1) * 2;
            pah[t][base + 0] = pack_bf2(p0, p1);
            pah[t][base + 1] = pack_bf2(p2, p3);
            pal[t][base + 0] = pack_bf2(p0 - h0, p1 - h1);
            pal[t][base + 1] = pack_bf2(p2 - h2, p3 - h3);
        }
        ps0 += __shfl_xor_sync(0xffffffffu, ps0, 1);
        ps0 += __shfl_xor_sync(0xffffffffu, ps0, 2);
        ps1 += __shfl_xor_sync(0xffffffffu, ps1, 1);
        ps1 += __shfl_xor_sync(0xffffffffu, ps1, 2);
        l0 = l0 * cr0 + ps0; m0 = mn0;
        l1 = l1 * cr1 + ps1; m1 = mn1;
        #pragma unroll
        for (int nt = 0; nt < 8; ++nt) {
            oacc[nt][0] *= cr0; oacc[nt][1] *= cr0;
            oacc[nt][2] *= cr1; oacc[nt][3] *= cr1;
        }

        // ---- PV: o[16q][64d] += P[16q][64s] V[64s][64d] (V^T via trans ldsm) --
        #pragma unroll
        for (int t = 0; t < 4; ++t) {           // s slices of 16
            #pragma unroll
            for (int g = 0; g < 4; ++g) {       // d pairs of 16
                int r = t * 16 + ((lane >> 3) & 1) * 8 + (lane & 7);
                int ch = g * 2 + (lane >> 4);
                uint32_t so = (uint32_t)(r * 128 + ((ch ^ (r & 7)) * 16));
                uint32_t vh[4], vl[4];
                LDSM4T(vh, Vh + so);
                LDSM4T(vl, Vl + so);
                MMA16816(oacc[g*2],     pah[t], &vh[0]);
                MMA16816(oacc[g*2],     pah[t], &vl[0]);
                MMA16816(oacc[g*2],     pal[t], &vh[0]);
                MMA16816(oacc[g*2 + 1], pah[t], &vh[2]);
                MMA16816(oacc[g*2 + 1], pah[t], &vl[2]);
                MMA16816(oacc[g*2 + 1], pal[t], &vh[2]);
            }
        }
    }

    // ---- epilogue: hi/lo bf16 out, stride EMB ----
    float i0 = 1.0f / l0, i1 = 1.0f / l1;
    size_t row0 = (size_t)(b * SEQ) + qBase + w * 16 + (lane >> 2);
    #pragma unroll
    for (int nt = 0; nt < 8; ++nt) {
        int col = h * HD + nt * 8 + (lane & 3) * 2;
        float v0 = oacc[nt][0] * i0, v1 = oacc[nt][1] * i0;
        float v2 = oacc[nt][2] * i1, v3 = oacc[nt][3] * i1;
        float h0 = __bfloat162float(__float2bfloat16(v0));
        float h1 = __bfloat162float(__float2bfloat16(v1));
        float h2 = __bfloat162float(__float2bfloat16(v2));
        float h3 = __bfloat162float(__float2bfloat16(v3));
        *(uint32_t*)(oh + row0 * EMB + col)       = pack_bf2(v0, v1);
        *(uint32_t*)(ol + row0 * EMB + col)       = pack_bf2(v0 - h0, v1 - h1);
        *(uint32_t*)(oh + (row0 + 8) * EMB + col) = pack_bf2(v2, v3);
        *(uint32_t*)(ol + (row0 + 8) * EMB + col) = pack_bf2(v2 - h2, v3 - h3);
    }
}

// ---------------- launch ----------------------------------------------------
extern "C" void kernel_launch(void* const* d_in, const int* in_sizes, int n_in,
                              void* d_out, int out_size) {
    const int*   idx    = (const int*)d_in[0];
    const float* tok    = (const float*)d_in[1];
    const float* pos    = (const float*)d_in[2];
    const float* Wq     = (const float*)d_in[3];
    const float* Wk     = (const float*)d_in[4];
    const float* Wv     = (const float*)d_in[5];
    const float* Wp     = (const float*)d_in[6];
    const float* bp     = (const float*)d_in[7];
    const float* ln1_g  = (const float*)d_in[8];
    const float* ln1_b  = (const float*)d_in[9];
    const float* ln2_g  = (const float*)d_in[10];
    const float* ln2_b  = (const float*)d_in[11];
    const float* W1     = (const float*)d_in[12];
    const float* b1     = (const float*)d_in[13];
    const float* W2     = (const float*)d_in[14];
    const float* b2     = (const float*)d_in[15];
    const float* lnf_g  = (const float*)d_in[16];
    const float* lnf_b  = (const float*)d_in[17];
    const float* Wout   = (const float*)d_in[18];

    float *x;
    bf16 *hh, *hl, *qkvh, *qkvl, *ohh, *ohl, *uh, *ul;
    bf16 *wqkvh, *wqkvl, *wph, *wpl, *w1h, *w1l, *w2h, *w2l, *woh, *wol;
    cudaGetSymbolAddress((void**)&x, g_x);
    cudaGetSymbolAddress((void**)&hh, g_h_h);
    cudaGetSymbolAddress((void**)&hl, g_h_l);
    cudaGetSymbolAddress((void**)&qkvh, g_qkv_h);
    cudaGetSymbolAddress((void**)&qkvl, g_qkv_l);
    cudaGetSymbolAddress((void**)&ohh, g_o_h);
    cudaGetSymbolAddress((void**)&ohl, g_o_l);
    cudaGetSymbolAddress((void**)&uh, g_u_h);
    cudaGetSymbolAddress((void**)&ul, g_u_l);
    cudaGetSymbolAddress((void**)&wqkvh, g_Wqkv_h); cudaGetSymbolAddress((void**)&wqkvl, g_Wqkv_l);
    cudaGetSymbolAddress((void**)&wph, g_Wp_h);     cudaGetSymbolAddress((void**)&wpl, g_Wp_l);
    cudaGetSymbolAddress((void**)&w1h, g_W1_h);     cudaGetSymbolAddress((void**)&w1l, g_W1_l);
    cudaGetSymbolAddress((void**)&w2h, g_W2_h);     cudaGetSymbolAddress((void**)&w2l, g_W2_l);
    cudaGetSymbolAddress((void**)&woh, g_Wo_h);     cudaGetSymbolAddress((void**)&wol, g_Wo_l);

    cudaFuncSetAttribute(mgemm6_kernel, cudaFuncAttributeMaxDynamicSharedMemorySize, MG_SMEM);
    cudaFuncSetAttribute(mattn_kernel, cudaFuncAttributeMaxDynamicSharedMemorySize, FA_SMEM);

    tconv_all<<<130304, dim3(32, 8)>>>(Wq, Wk, Wv, Wp, W1, W2, Wout,
                                       wqkvh, wqkvl, wph, wpl, w1h, w1l,
                                       w2h, w2l, woh, wol);
    embed_kernel<<<NTOK, 256>>>(idx, tok, pos, x);

    dim3 gQKV(NTOK / 128, 3 * EMB / 128);
    dim3 gE(NTOK / 128, EMB / 128);
    dim3 gH(NTOK / 128, HID / 128);
    dim3 gV(NTOK / 128, VOCAB / 128);
    dim3 gA(SEQ / 64, 2 * NH);

    for (int l = 0; l < NL; l++) {
        size_t wo = (size_t)l * EMB * EMB;
        size_t wqo = (size_t)l * 3 * EMB * EMB;
        size_t w1o = (size_t)l * EMB * HID;

        ln_kernel<<<NTOK, 256>>>(x, ln1_g + l * EMB, ln1_b + l * EMB, hh, hl);
        mgemm6_kernel<<<gQKV, 512, MG_SMEM>>>(hh, hl, wqkvh + wqo, wqkvl + wqo,
                                              nullptr, nullptr, nullptr, qkvh, qkvl,
                                              NTOK, 3 * EMB, EMB, FLAG_OSPL);
        mattn_kernel<<<gA, 128, FA_SMEM>>>(qkvh, qkvl, ohh, ohl);
        mgemm6_kernel<<<gE, 512, MG_SMEM>>>(ohh, ohl, wph + wo, wpl + wo, bp + l * EMB, x,
                                            x, nullptr, nullptr, NTOK, EMB, EMB,
                                            FLAG_BIAS | FLAG_RES);
        ln_kernel<<<NTOK, 256>>>(x, ln2_g + l * EMB, ln2_b + l * EMB, hh, hl);
        mgemm6_kernel<<<gH, 512, MG_SMEM>>>(hh, hl, w1h + w1o, w1l + w1o, b1 + l * HID,
                                            nullptr, nullptr, uh, ul, NTOK, HID, EMB,
                                            FLAG_BIAS | FLAG_GELU | FLAG_OSPL);
        mgemm6_kernel<<<gE, 512, MG_SMEM>>>(uh, ul, w2h + w1o, w2l + w1o, b2 + l * EMB, x,
                                            x, nullptr, nullptr, NTOK, EMB, HID,
                                            FLAG_BIAS | FLAG_RES);
    }

    ln_kernel<<<NTOK, 256>>>(x, lnf_g, lnf_b, hh, hl);
    mgemm6_kernel<<<gV, 512, MG_SMEM>>>(hh, hl, woh, wol, nullptr, nullptr,
                                        (float*)d_out, nullptr, nullptr,
                                        NTOK, VOCAB, EMB, 0);
}

// round 14
// speedup vs baseline: 1.4244x; 1.0008x over previous
#include <cuda_runtime.h>
#include <cuda_bf16.h>
#include <math.h>
#include <stdint.h>

#define NTOK 4096
#define EMB  1024
#define HID  4096
#define VOCAB 32000
#define SEQ  2048
#define NH   16
#define HD   64
#define NL   8

typedef __nv_bfloat16 bf16;
typedef __nv_bfloat162 bf162;

// ---------------- device scratch --------------------------------------------
__device__ __align__(16) float g_x[NTOK * EMB];

__device__ __align__(16) bf16 g_h_h[NTOK * EMB];
__device__ __align__(16) bf16 g_h_l[NTOK * EMB];
__device__ __align__(16) bf16 g_qkv_h[NTOK * 3 * EMB];
__device__ __align__(16) bf16 g_qkv_l[NTOK * 3 * EMB];
__device__ __align__(16) bf16 g_o_h[NTOK * EMB];
__device__ __align__(16) bf16 g_o_l[NTOK * EMB];
__device__ __align__(16) bf16 g_u_h[NTOK * HID];
__device__ __align__(16) bf16 g_u_l[NTOK * HID];

// transposed weights [N][K] hi/lo; QKV fused to [3E][E] per layer
__device__ __align__(16) bf16 g_Wqkv_h[NL * 3 * EMB * EMB];
__device__ __align__(16) bf16 g_Wqkv_l[NL * 3 * EMB * EMB];
__device__ __align__(16) bf16 g_Wp_h[NL * EMB * EMB];
__device__ __align__(16) bf16 g_Wp_l[NL * EMB * EMB];
__device__ __align__(16) bf16 g_W1_h[NL * EMB * HID];
__device__ __align__(16) bf16 g_W1_l[NL * EMB * HID];
__device__ __align__(16) bf16 g_W2_h[NL * EMB * HID];
__device__ __align__(16) bf16 g_W2_l[NL * EMB * HID];
__device__ __align__(16) bf16 g_Wo_h[(size_t)VOCAB * EMB];
__device__ __align__(16) bf16 g_Wo_l[(size_t)VOCAB * EMB];

// ---------------- helpers ---------------------------------------------------
__device__ __forceinline__ uint32_t smem_u32(const void* p) {
    return (uint32_t)__cvta_generic_to_shared((void*)p);
}
__device__ __forceinline__ uint32_t pack_bf2(float a, float b) {
    bf162 t = __floats2bfloat162_rn(a, b);
    return *reinterpret_cast<uint32_t*>(&t);
}
__device__ __forceinline__ void cpa16(uint32_t dst, const void* src) {
    asm volatile("cp.async.ca.shared.global [%0], [%1], 16;" :: "r"(dst), "l"(src));
}
#define CPA_COMMIT() asm volatile("cp.async.commit_group;" ::: "memory")
#define CPA_WAIT1()  asm volatile("cp.async.wait_group 1;" ::: "memory")
#define CPA_WAIT0()  asm volatile("cp.async.wait_group 0;" ::: "memory")

#define LDSM4(r, a) \
    asm volatile("ldmatrix.sync.aligned.m8n8.x4.shared.b16 {%0,%1,%2,%3}, [%4];" \
        : "=r"((r)[0]), "=r"((r)[1]), "=r"((r)[2]), "=r"((r)[3]) : "r"(a))

#define LDSM4T(r, a) \
    asm volatile("ldmatrix.sync.aligned.m8n8.x4.trans.shared.b16 {%0,%1,%2,%3}, [%4];" \
        : "=r"((r)[0]), "=r"((r)[1]), "=r"((r)[2]), "=r"((r)[3]) : "r"(a))

#define MMA16816(d, a, b) \
    asm volatile("mma.sync.aligned.m16n8k16.row.col.f32.bf16.bf16.f32 " \
        "{%0,%1,%2,%3},{%4,%5,%6,%7},{%8,%9},{%0,%1,%2,%3};" \
        : "+f"((d)[0]), "+f"((d)[1]), "+f"((d)[2]), "+f"((d)[3]) \
        : "r"((a)[0]), "r"((a)[1]), "r"((a)[2]), "r"((a)[3]), \
          "r"((b)[0]), "r"((b)[1]))

// ---------------- all-weights transpose + split-convert ----------------------
__global__ void tconv_all(const float* __restrict__ Wq, const float* __restrict__ Wk,
                          const float* __restrict__ Wv, const float* __restrict__ Wp,
                          const float* __restrict__ W1, const float* __restrict__ W2,
                          const float* __restrict__ Wout,
                          bf16* __restrict__ qkvh, bf16* __restrict__ qkvl,
                          bf16* __restrict__ wph, bf16* __restrict__ wpl,
                          bf16* __restrict__ w1h, bf16* __restrict__ w1l,
                          bf16* __restrict__ w2h, bf16* __restrict__ w2l,
                          bf16* __restrict__ woh, bf16* __restrict__ wol) {
    __shared__ float t[32][33];
    int b = blockIdx.x;
    const float* src; bf16 *oh, *ol;
    int K, N, tilesX, tloc, rowOff = 0;

    if (b < 24576) {
        int type = b / 8192, lb = b % 8192;
        int layer = lb / 1024; tloc = lb % 1024;
        K = 1024; N = 1024; tilesX = 32;
        src = (type == 0 ? Wq : type == 1 ? Wk : Wv) + (size_t)layer * EMB * EMB;
        oh = qkvh + (size_t)layer * 3 * EMB * EMB;
        ol = qkvl + (size_t)layer * 3 * EMB * EMB;
        rowOff = type * 1024;
    } else if (b < 32768) {
        int lb = b - 24576;
        int layer = lb / 1024; tloc = lb % 1024;
        K = 1024; N = 1024; tilesX = 32;
        src = Wp + (size_t)layer * EMB * EMB;
        oh = wph + (size_t)layer * EMB * EMB;
        ol = wpl + (size_t)layer * EMB * EMB;
    } else if (b < 65536) {
        int lb = b - 32768;
        int layer = lb / 4096; tloc = lb % 4096;
        K = 1024; N = 4096; tilesX = 128;
        src = W1 + (size_t)layer * EMB * HID;
        oh = w1h + (size_t)layer * EMB * HID;
        ol = w1l + (size_t)layer * EMB * HID;
    } else if (b < 98304) {
        int lb = b - 65536;
        int layer = lb / 4096; tloc = lb % 4096;
        K = 4096; N = 1024; tilesX = 32;
        src = W2 + (size_t)layer * HID * EMB;
        oh = w2h + (size_t)layer * HID * EMB;
        ol = w2l + (size_t)layer * HID * EMB;
    } else {
        tloc = b - 98304;
        K = 1024; N = VOCAB; tilesX = 1000;
        src = Wout; oh = woh; ol = wol;
    }

    int bx = (tloc % tilesX) * 32;
    int by = (tloc / tilesX) * 32;
    int x = threadIdx.x, y = threadIdx.y;
    #pragma unroll
    for (int i = 0; i < 4; i++)
        t[y + i * 8][x] = src[(size_t)(by + y + i * 8) * N + bx + x];
    __syncthreads();
    #pragma unroll
    for (int i = 0; i < 4; i++) {
        int n = bx + y + i * 8, k = by + x;
        float v = t[x][y + i * 8];
        bf16 hv = __float2bfloat16(v);
        oh[(size_t)(rowOff + n) * K + k] = hv;
        ol[(size_t)(rowOff + n) * K + k] = __float2bfloat16(v - __bfloat162float(hv));
    }
}

// ---------------- embed ------------------------------------------------------
__global__ void embed_kernel(const int* __restrict__ idx, const float* __restrict__ tok,
                             const float* __restrict__ pos, float* __restrict__ x) {
    int n = blockIdx.x, e4 = threadIdx.x, t = n & (SEQ - 1);
    float4 a = ((const float4*)(tok + (size_t)idx[n] * EMB))[e4];
    float4 b = ((const float4*)(pos + (size_t)t * EMB))[e4];
    a.x += b.x; a.y += b.y; a.z += b.z; a.w += b.w;
    ((float4*)(x + (size_t)n * EMB))[e4] = a;
}

// ---------------- layernorm -> hi/lo bf16 ------------------------------------
__device__ __forceinline__ float block_sum_256(float s, float* red) {
    #pragma unroll
    for (int o = 16; o; o >>= 1) s += __shfl_xor_sync(0xffffffffu, s, o);
    if ((threadIdx.x & 31) == 0) red[threadIdx.x >> 5] = s;
    __syncthreads();
    if (threadIdx.x < 32) {
        float t = (threadIdx.x < 8) ? red[threadIdx.x] : 0.0f;
        #pragma unroll
        for (int o = 4; o; o >>= 1) t += __shfl_xor_sync(0xffffffffu, t, o);
        if (threadIdx.x == 0) red[0] = t;
    }
    __syncthreads();
    float r = red[0];
    __syncthreads();
    return r;
}

__global__ void ln_kernel(const float* __restrict__ x, const float* __restrict__ g,
                          const float* __restrict__ b, bf16* __restrict__ oh,
                          bf16* __restrict__ ol) {
    __shared__ float red[8];
    int n = blockIdx.x, tid = threadIdx.x;
    float4 v = ((const float4*)(x + (size_t)n * EMB))[tid];
    float mu = block_sum_256(v.x + v.y + v.z + v.w, red) * (1.0f / EMB);
    float dx = v.x - mu, dy = v.y - mu, dz = v.z - mu, dw = v.w - mu;
    float var = block_sum_256(dx*dx + dy*dy + dz*dz + dw*dw, red) * (1.0f / EMB);
    float rs = rsqrtf(var + 1e-5f);
    float4 gg = ((const float4*)g)[tid];
    float4 bb = ((const float4*)b)[tid];
    float r0 = dx*rs*gg.x + bb.x, r1 = dy*rs*gg.y + bb.y;
    float r2 = dz*rs*gg.z + bb.z, r3 = dw*rs*gg.w + bb.w;
    float h0 = __bfloat162float(__float2bfloat16(r0));
    float h1 = __bfloat162float(__float2bfloat16(r1));
    float h2 = __bfloat162float(__float2bfloat16(r2));
    float h3 = __bfloat162float(__float2bfloat16(r3));
    size_t o = (size_t)n * EMB + tid * 4;
    *(uint2*)(oh + o) = make_uint2(pack_bf2(r0, r1), pack_bf2(r2, r3));
    *(uint2*)(ol + o) = make_uint2(pack_bf2(r0 - h0, r1 - h1), pack_bf2(r2 - h2, r3 - h3));
}

// ============= 16-warp cross-stage-pipelined split-bf16 MMA GEMM =============
// (exact mgemm6 from R9 — best measured GEMM)
#define FLAG_BIAS 1
#define FLAG_GELU 2
#define FLAG_RES  4
#define FLAG_OSPL 8
#define MG_SMEM (4 * 32768)

__global__ __launch_bounds__(512, 1) void mgemm6_kernel(
    const bf16* __restrict__ Ah, const bf16* __restrict__ Al,
    const bf16* __restrict__ Bh, const bf16* __restrict__ Bl,
    const float* __restrict__ bias, const float* __restrict__ res,
    float* __restrict__ C, bf16* __restrict__ Oh, bf16* __restrict__ Ol,
    int M, int N, int K, int flags) {
    extern __shared__ char sm[];
    uint32_t smb = smem_u32(sm);

    int tid = threadIdx.x;
    int lane = tid & 31, wid = tid >> 5;
    int warp_m = wid >> 2, warp_n = wid & 3;
    int rowBase = blockIdx.x * 128, colBase = blockIdx.y * 128;

    float acc[2][4][4];
    #pragma unroll
    for (int i = 0; i < 2; i++)
        #pragma unroll
        for (int j = 0; j < 4; j++)
            #pragma unroll
            for (int q = 0; q < 4; q++) acc[i][j][q] = 0.0f;

    uint32_t offA[2][2][2], offB[2][2][2];
    #pragma unroll
    for (int kk = 0; kk < 2; ++kk) {
        #pragma unroll
        for (int mt = 0; mt < 2; ++mt) {
            int r = warp_m * 32 + mt * 16 + (lane & 15);
            int ch = kk * 2 + (lane >> 4);
            offA[kk][mt][0] = (uint32_t)(r * 128 + ((ch ^ (r & 7)) * 16));
            offA[kk][mt][1] = (uint32_t)(r * 128 + (((ch + 4) ^ (r & 7)) * 16));
        }
        #pragma unroll
        for (int g2 = 0; g2 < 2; ++g2) {
            int n = warp_n * 32 + g2 * 16 + ((lane >> 4) << 3) + (lane & 7);
            int ch = kk * 2 + ((lane >> 3) & 1);
            offB[kk][g2][0] = (uint32_t)(16384 + n * 128 + ((ch ^ (n & 7)) * 16));
            offB[kk][g2][1] = (uint32_t)(16384 + n * 128 + (((ch + 4) ^ (n & 7)) * 16));
        }
    }

    int S = K >> 5;

    auto load_stage = [&](int s, int buf) {
        uint32_t sb = smb + buf * 32768;
        const bf16* gAh = Ah + (size_t)rowBase * K + s * 32;
        const bf16* gAl = Al + (size_t)rowBase * K + s * 32;
        const bf16* gBh = Bh + (size_t)colBase * K + s * 32;
        const bf16* gBl = Bl + (size_t)colBase * K + s * 32;
        #pragma unroll
        for (int i = 0; i < 2; i++) {
            int f = tid + i * 512;
            int r = f >> 3, c = f & 7;
            uint32_t so = (uint32_t)(r * 128 + ((c ^ (r & 7)) * 16));
            const bf16* srcA = (c < 4) ? (gAh + (size_t)r * K + c * 8)
                                       : (gAl + (size_t)r * K + (c - 4) * 8);
            const bf16* srcB = (c < 4) ? (gBh + (size_t)r * K + c * 8)
                                       : (gBl + (size_t)r * K + (c - 4) * 8);
            cpa16(sb + so, srcA);
            cpa16(sb + 16384 + so, srcB);
        }
        CPA_COMMIT();
    };

    uint32_t ah[2][2][4], al[2][2][4], bh[2][8], bl[2][8];

    auto ldfrags = [&](int fb, int kk, uint32_t sb) {
        #pragma unroll
        for (int mt = 0; mt < 2; ++mt) {
            LDSM4(ah[fb][mt], sb + offA[kk][mt][0]);
            LDSM4(al[fb][mt], sb + offA[kk][mt][1]);
        }
        #pragma unroll
        for (int g2 = 0; g2 < 2; ++g2) {
            LDSM4(&bh[fb][g2 * 4], sb + offB[kk][g2][0]);
            LDSM4(&bl[fb][g2 * 4], sb + offB[kk][g2][1]);
        }
    };

    auto do_mma = [&](int fb) {
        #pragma unroll
        for (int mt = 0; mt < 2; ++mt)
            #pragma unroll
            for (int nt = 0; nt < 4; ++nt) {
                uint32_t* ph = &bh[fb][(nt >> 1) * 4 + (nt & 1) * 2];
                uint32_t* pl = &bl[fb][(nt >> 1) * 4 + (nt & 1) * 2];
                MMA16816(acc[mt][nt], ah[fb][mt], ph);
                MMA16816(acc[mt][nt], ah[fb][mt], pl);
                MMA16816(acc[mt][nt], al[fb][mt], ph);
            }
    };

    load_stage(0, 0);
    load_stage(1, 1);
    load_stage(2, 2);
    CPA_WAIT1();
    __syncthreads();
    ldfrags(0, 0, smb);

    for (int s = 0; s < S; ++s) {
        uint32_t sb = smb + (s & 3) * 32768;

        if (s + 3 < S) load_stage(s + 3, (s + 3) & 3);
        else CPA_COMMIT();

        ldfrags(1, 1, sb);
        do_mma(0);

        CPA_WAIT1();
        if (s + 1 < S)
            ldfrags(0, 0, smb + ((s + 1) & 3) * 32768);
        do_mma(1);
        __syncthreads();
    }

    #pragma unroll
    for (int mt = 0; mt < 2; ++mt) {
        #pragma unroll
        for (int nt = 0; nt < 4; ++nt) {
            int col = colBase + warp_n * 32 + nt * 8 + (lane & 3) * 2;
            int row0 = rowBase + warp_m * 32 + mt * 16 + (lane >> 2);
            #pragma unroll
            for (int half = 0; half < 2; ++half) {
                size_t row = (size_t)(row0 + half * 8);
                float v0 = acc[mt][nt][half * 2 + 0];
                float v1 = acc[mt][nt][half * 2 + 1];
                if (flags & FLAG_BIAS) { v0 += bias[col]; v1 += bias[col + 1]; }
                if (flags & FLAG_GELU) {
                    v0 = 0.5f * v0 * (1.0f + erff(v0 * 0.70710678118654752f));
                    v1 = 0.5f * v1 * (1.0f + erff(v1 * 0.70710678118654752f));
                }
                if (flags & FLAG_RES) {
                    float2 rv = *(const float2*)(res + row * N + col);
                    v0 += rv.x; v1 += rv.y;
                }
                if (flags & FLAG_OSPL) {
                    float h0 = __bfloat162float(__float2bfloat16(v0));
                    float h1 = __bfloat162float(__float2bfloat16(v1));
                    *(uint32_t*)(Oh + row * N + col) = pack_bf2(v0, v1);
                    *(uint32_t*)(Ol + row * N + col) = pack_bf2(v0 - h0, v1 - h1);
                } else {
                    *(float2*)(C + row * N + col) = make_float2(v0, v1);
                }
            }
        }
    }
}

// ============== MMA flash attention (split-bf16, 4 warps, 64-q tile) =========
// qkv hi/lo: [NTOK][3072]. smem: Qh Ql Kh Kl Vh Vl, each 64 rows x 128B swizzled.
#define FA_SMEM 49152
#define QKVS 3072

__global__ __launch_bounds__(128) void mattn_kernel(
    const bf16* __restrict__ qkvh, const bf16* __restrict__ qkvl,
    bf16* __restrict__ oh, bf16* __restrict__ ol) {
    extern __shared__ char smc[];
    uint32_t smb = smem_u32(smc);
    uint32_t Qh = smb, Ql = smb + 8192;
    uint32_t Kh = smb + 16384, Kl = smb + 24576;
    uint32_t Vh = smb + 32768, Vl = smb + 40960;

    int qt = gridDim.x - 1 - blockIdx.x;   // long blocks first
    int bh = blockIdx.y;
    int b = bh >> 4, h = bh & 15;
    int tid = threadIdx.x, lane = tid & 31, w = tid >> 5;
    int qBase = qt * 64;
    size_t rowQ = (size_t)(b * SEQ + qBase);

    // stage Q (hi/lo)
    #pragma unroll
    for (int i = 0; i < 4; ++i) {
        int f = tid + i * 128;
        int r = f >> 3, c = f & 7;
        uint32_t so = (uint32_t)(r * 128 + ((c ^ (r & 7)) * 16));
        size_t g = (rowQ + r) * QKVS + h * HD + c * 8;
        cpa16(Qh + so, qkvh + g);
        cpa16(Ql + so, qkvl + g);
    }
    CPA_COMMIT();

    float m0 = -1e30f, m1 = -1e30f, l0 = 0.0f, l1 = 0.0f;
    float oacc[8][4];
    #pragma unroll
    for (int nt = 0; nt < 8; ++nt)
        #pragma unroll
        for (int e = 0; e < 4; ++e) oacc[nt][e] = 0.0f;

    int r0g = qBase + w * 16 + (lane >> 2);    // global q row (half 0)

    for (int kt = 0; kt <= qt; ++kt) {
        int kBase = kt * 64;
        size_t rowK = (size_t)(b * SEQ + kBase);
        __syncthreads();                        // prior K/V reads done
        #pragma unroll
        for (int i = 0; i < 4; ++i) {
            int f = tid + i * 128;
            int r = f >> 3, c = f & 7;
            uint32_t so = (uint32_t)(r * 128 + ((c ^ (r & 7)) * 16));
            size_t gk = (rowK + r) * QKVS + 1024 + h * HD + c * 8;
            cpa16(Kh + so, qkvh + gk);
            cpa16(Kl + so, qkvl + gk);
            cpa16(Vh + so, qkvh + gk + 1024);
            cpa16(Vl + so, qkvl + gk + 1024);
        }
        CPA_COMMIT();
        CPA_WAIT0();
        __syncthreads();

        // ---- QK^T: sacc[8 ntiles][4] ----
        float sacc[8][4];
        #pragma unroll
        for (int nt = 0; nt < 8; ++nt)
            #pragma unroll
            for (int e = 0; e < 4; ++e) sacc[nt][e] = 0.0f;

        #pragma unroll
        for (int kk = 0; kk < 4; ++kk) {        // d slices of 16
            uint32_t aq[4], aql[4];
            {
                int r = w * 16 + (lane & 15);
                int ch = kk * 2 + (lane >> 4);
                uint32_t so = (uint32_t)(r * 128 + ((ch ^ (r & 7)) * 16));
                LDSM4(aq, Qh + so);
                LDSM4(aql, Ql + so);
            }
            #pragma unroll
            for (int g2 = 0; g2 < 4; ++g2) {    // s groups of 16
                int n = g2 * 16 + ((lane >> 4) << 3) + (lane & 7);
                int ch = kk * 2 + ((lane >> 3) & 1);
                uint32_t so = (uint32_t)(n * 128 + ((ch ^ (n & 7)) * 16));
                uint32_t bk[4], bkl[4];
                LDSM4(bk, Kh + so);
                LDSM4(bkl, Kl + so);
                MMA16816(sacc[g2*2],     aq,  &bk[0]);
                MMA16816(sacc[g2*2],     aq,  &bkl[0]);
                MMA16816(sacc[g2*2],     aql, &bk[0]);
                MMA16816(sacc[g2*2 + 1], aq,  &bk[2]);
                MMA16816(sacc[g2*2 + 1], aq,  &bkl[2]);
                MMA16816(sacc[g2*2 + 1], aql, &bk[2]);
            }
        }

        // ---- softmax (rows lane>>2 and +8) ----
        bool diag = (kt == qt);
        float mx0 = -1e30f, mx1 = -1e30f;
        #pragma unroll
        for (int nt = 0; nt < 8; ++nt) {
            int c0 = kBase + nt * 8 + (lane & 3) * 2;
            #pragma unroll
            for (int e = 0; e < 2; ++e) {
                float v0 = sacc[nt][e] * 0.125f;
                float v1 = sacc[nt][2 + e] * 0.125f;
                if (diag) {
                    if (c0 + e > r0g)     v0 = -1e30f;
                    if (c0 + e > r0g + 8) v1 = -1e30f;
                }
                sacc[nt][e] = v0; sacc[nt][2 + e] = v1;
                mx0 = fmaxf(mx0, v0); mx1 = fmaxf(mx1, v1);
            }
        }
        mx0 = fmaxf(mx0, __shfl_xor_sync(0xffffffffu, mx0, 1));
        mx0 = fmaxf(mx0, __shfl_xor_sync(0xffffffffu, mx0, 2));
        mx1 = fmaxf(mx1, __shfl_xor_sync(0xffffffffu, mx1, 1));
        mx1 = fmaxf(mx1, __shfl_xor_sync(0xffffffffu, mx1, 2));
        float mn0 = fmaxf(m0, mx0), mn1 = fmaxf(m1, mx1);
        float cr0 = __expf(m0 - mn0), cr1 = __expf(m1 - mn1);
        float ps0 = 0.0f, ps1 = 0.0f;
        uint32_t pah[4][4], pal[4][4];
        #pragma unroll
        for (int nt = 0; nt < 8; ++nt) {
            float p0 = __expf(sacc[nt][0] - mn0);
            float p1 = __expf(sacc[nt][1] - mn0);
            float p2 = __expf(sacc[nt][2] - mn1);
            float p3 = __expf(sacc[nt][3] - mn1);
            ps0 += p0 + p1; ps1 += p2 + p3;
            float h0 = __bfloat162float(__float2bfloat16(p0));
            float h1 = __bfloat162float(__float2bfloat16(p1));
            float h2 = __bfloat162float(__float2bfloat16(p2));
            float h3 = __bfloat162float(__float2bfloat16(p3));
            int t = nt >> 1, base = (nt & 1) * 2;
            pah[t][base + 0] = pack_bf2(p0, p1);
            pah[t][base + 1] = pack_bf2(p2, p3);
            pal[t][base + 0] = pack_bf2(p0 - h0, p1 - h1);
            pal[t][base + 1] = pack_bf2(p2 - h2, p3 - h3);
        }
        ps0 += __shfl_xor_sync(0xffffffffu, ps0, 1);
        ps0 += __shfl_xor_sync(0xffffffffu, ps0, 2);
        ps1 += __shfl_xor_sync(0xffffffffu, ps1, 1);
        ps1 += __shfl_xor_sync(0xffffffffu, ps1, 2);
        l0 = l0 * cr0 + ps0; m0 = mn0;
        l1 = l1 * cr1 + ps1; m1 = mn1;
        #pragma unroll
        for (int nt = 0; nt < 8; ++nt) {
            oacc[nt][0] *= cr0; oacc[nt][1] *= cr0;
            oacc[nt][2] *= cr1; oacc[nt][3] *= cr1;
        }

        // ---- PV: o[16q][64d] += P[16q][64s] V[64s][64d] (V^T via trans ldsm) --
        #pragma unroll
        for (int t = 0; t < 4; ++t) {           // s slices of 16
            #pragma unroll
            for (int g = 0; g < 4; ++g) {       // d pairs of 16
                int r = t * 16 + ((lane >> 3) & 1) * 8 + (lane & 7);
                int ch = g * 2 + (lane >> 4);
                uint32_t so = (uint32_t)(r * 128 + ((ch ^ (r & 7)) * 16));
                uint32_t vh[4], vl[4];
                LDSM4T(vh, Vh + so);
                LDSM4T(vl, Vl + so);
                MMA16816(oacc[g*2],     pah[t], &vh[0]);
                MMA16816(oacc[g*2],     pah[t], &vl[0]);
                MMA16816(oacc[g*2],     pal[t], &vh[0]);
                MMA16816(oacc[g*2 + 1], pah[t], &vh[2]);
                MMA16816(oacc[g*2 + 1], pah[t], &vl[2]);
                MMA16816(oacc[g*2 + 1], pal[t], &vh[2]);
            }
        }
    }

    // ---- epilogue: hi/lo bf16 out, stride EMB ----
    float i0 = 1.0f / l0, i1 = 1.0f / l1;
    size_t row0 = (size_t)(b * SEQ) + qBase + w * 16 + (lane >> 2);
    #pragma unroll
    for (int nt = 0; nt < 8; ++nt) {
        int col = h * HD + nt * 8 + (lane & 3) * 2;
        float v0 = oacc[nt][0] * i0, v1 = oacc[nt][1] * i0;
        float v2 = oacc[nt][2] * i1, v3 = oacc[nt][3] * i1;
        float h0 = __bfloat162float(__float2bfloat16(v0));
        float h1 = __bfloat162float(__float2bfloat16(v1));
        float h2 = __bfloat162float(__float2bfloat16(v2));
        float h3 = __bfloat162float(__float2bfloat16(v3));
        *(uint32_t*)(oh + row0 * EMB + col)       = pack_bf2(v0, v1);
        *(uint32_t*)(ol + row0 * EMB + col)       = pack_bf2(v0 - h0, v1 - h1);
        *(uint32_t*)(oh + (row0 + 8) * EMB + col) = pack_bf2(v2, v3);
        *(uint32_t*)(ol + (row0 + 8) * EMB + col) = pack_bf2(v2 - h2, v3 - h3);
    }
}

// ---------------- launch ----------------------------------------------------
extern "C" void kernel_launch(void* const* d_in, const int* in_sizes, int n_in,
                              void* d_out, int out_size) {
    const int*   idx    = (const int*)d_in[0];
    const float* tok    = (const float*)d_in[1];
    const float* pos    = (const float*)d_in[2];
    const float* Wq     = (const float*)d_in[3];
    const float* Wk     = (const float*)d_in[4];
    const float* Wv     = (const float*)d_in[5];
    const float* Wp     = (const float*)d_in[6];
    const float* bp     = (const float*)d_in[7];
    const float* ln1_g  = (const float*)d_in[8];
    const float* ln1_b  = (const float*)d_in[9];
    const float* ln2_g  = (const float*)d_in[10];
    const float* ln2_b  = (const float*)d_in[11];
    const float* W1     = (const float*)d_in[12];
    const float* b1     = (const float*)d_in[13];
    const float* W2     = (const float*)d_in[14];
    const float* b2     = (const float*)d_in[15];
    const float* lnf_g  = (const float*)d_in[16];
    const float* lnf_b  = (const float*)d_in[17];
    const float* Wout   = (const float*)d_in[18];

    float *x;
    bf16 *hh, *hl, *qkvh, *qkvl, *ohh, *ohl, *uh, *ul;
    bf16 *wqkvh, *wqkvl, *wph, *wpl, *w1h, *w1l, *w2h, *w2l, *woh, *wol;
    cudaGetSymbolAddress((void**)&x, g_x);
    cudaGetSymbolAddress((void**)&hh, g_h_h);
    cudaGetSymbolAddress((void**)&hl, g_h_l);
    cudaGetSymbolAddress((void**)&qkvh, g_qkv_h);
    cudaGetSymbolAddress((void**)&qkvl, g_qkv_l);
    cudaGetSymbolAddress((void**)&ohh, g_o_h);
    cudaGetSymbolAddress((void**)&ohl, g_o_l);
    cudaGetSymbolAddress((void**)&uh, g_u_h);
    cudaGetSymbolAddress((void**)&ul, g_u_l);
    cudaGetSymbolAddress((void**)&wqkvh, g_Wqkv_h); cudaGetSymbolAddress((void**)&wqkvl, g_Wqkv_l);
    cudaGetSymbolAddress((void**)&wph, g_Wp_h);     cudaGetSymbolAddress((void**)&wpl, g_Wp_l);
    cudaGetSymbolAddress((void**)&w1h, g_W1_h);     cudaGetSymbolAddress((void**)&w1l, g_W1_l);
    cudaGetSymbolAddress((void**)&w2h, g_W2_h);     cudaGetSymbolAddress((void**)&w2l, g_W2_l);
    cudaGetSymbolAddress((void**)&woh, g_Wo_h);     cudaGetSymbolAddress((void**)&wol, g_Wo_l);

    cudaFuncSetAttribute(mgemm6_kernel, cudaFuncAttributeMaxDynamicSharedMemorySize, MG_SMEM);
    cudaFuncSetAttribute(mattn_kernel, cudaFuncAttributeMaxDynamicSharedMemorySize, FA_SMEM);

    tconv_all<<<130304, dim3(32, 8)>>>(Wq, Wk, Wv, Wp, W1, W2, Wout,
                                       wqkvh, wqkvl, wph, wpl, w1h, w1l,
                                       w2h, w2l, woh, wol);
    embed_kernel<<<NTOK, 256>>>(idx, tok, pos, x);

    dim3 gQKV(NTOK / 128, 3 * EMB / 128);
    dim3 gE(NTOK / 128, EMB / 128);
    dim3 gH(NTOK / 128, HID / 128);
    dim3 gV(NTOK / 128, VOCAB / 128);
    dim3 gA(SEQ / 64, 2 * NH);

    for (int l = 0; l < NL; l++) {
        size_t wo = (size_t)l * EMB * EMB;
        size_t wqo = (size_t)l * 3 * EMB * EMB;
        size_t w1o = (size_t)l * EMB * HID;

        ln_kernel<<<NTOK, 256>>>(x, ln1_g + l * EMB, ln1_b + l * EMB, hh, hl);
        mgemm6_kernel<<<gQKV, 512, MG_SMEM>>>(hh, hl, wqkvh + wqo, wqkvl + wqo,
                                              nullptr, nullptr, nullptr, qkvh, qkvl,
                                              NTOK, 3 * EMB, EMB, FLAG_OSPL);
        mattn_kernel<<<gA, 128, FA_SMEM>>>(qkvh, qkvl, ohh, ohl);
        mgemm6_kernel<<<gE, 512, MG_SMEM>>>(ohh, ohl, wph + wo, wpl + wo, bp + l * EMB, x,
                                            x, nullptr, nullptr, NTOK, EMB, EMB,
                                            FLAG_BIAS | FLAG_RES);
        ln_kernel<<<NTOK, 256>>>(x, ln2_g + l * EMB, ln2_b + l * EMB, hh, hl);
        mgemm6_kernel<<<gH, 512, MG_SMEM>>>(hh, hl, w1h + w1o, w1l + w1o, b1 + l * HID,
                                            nullptr, nullptr, uh, ul, NTOK, HID, EMB,
                                            FLAG_BIAS | FLAG_GELU | FLAG_OSPL);
        mgemm6_kernel<<<gE, 512, MG_SMEM>>>(uh, ul, w2h + w1o, w2l + w1o, b2 + l * EMB, x,
                                            x, nullptr, nullptr, NTOK, EMB, HID,
                                            FLAG_BIAS | FLAG_RES);
    }

    ln_kernel<<<NTOK, 256>>>(x, lnf_g, lnf_b, hh, hl);
    mgemm6_kernel<<<gV, 512, MG_SMEM>>>(hh, hl, woh, wol, nullptr, nullptr,
                                        (float*)d_out, nullptr, nullptr,
                                        NTOK, VOCAB, EMB, 0);
}